// round 6
// baseline (speedup 1.0000x reference)
#include <cuda_runtime.h>
#include <stdint.h>

// Problem dims
#define BB 4
#define SS 2048
#define DD 768
#define DQ 64
#define HH 3072
#define RR 8192   // BB*SS

// ---------------- scratch (device globals; no allocation allowed) ----------
__device__ float g_h   [RR*DD];
__device__ float g_h2  [RR*DD];
__device__ float g_y1  [RR*DD];
__device__ float g_qkv [RR*256];      // packed q|k|v|pad, row stride 256 (tf32)
__device__ float g_oh  [RR*DQ];
__device__ float g_a1  [(long long)RR*HH];
__device__ float g_ws  [DQ*DD];
__device__ float g_wqkv[DD*256];
__device__ float g_f1  [DD*HH];
__device__ float g_f2  [HH*DD];

__device__ __forceinline__ float to_tf32(float x) {
    float r;
    asm("cvt.rna.tf32.f32 %0, %1;\n" : "=f"(r) : "f"(x));
    return r;
}

__device__ __forceinline__ void cp16(void* dst, const float* src) {
    uint32_t d = (uint32_t)__cvta_generic_to_shared(dst);
    asm volatile("cp.async.cg.shared.global [%0], [%1], 16;\n" :: "r"(d), "l"(src));
}
#define CP_COMMIT() asm volatile("cp.async.commit_group;\n" ::: "memory")
#define CP_WAITG(n) asm volatile("cp.async.wait_group %0;\n" :: "n"(n) : "memory")

__device__ __forceinline__ void mma_tf32(float* c, const uint32_t* a, const uint32_t* b) {
    asm volatile(
        "mma.sync.aligned.m16n8k8.row.col.f32.tf32.tf32.f32 "
        "{%0,%1,%2,%3}, {%4,%5,%6,%7}, {%8,%9}, {%0,%1,%2,%3};\n"
        : "+f"(c[0]), "+f"(c[1]), "+f"(c[2]), "+f"(c[3])
        : "r"(a[0]), "r"(a[1]), "r"(a[2]), "r"(a[3]), "r"(b[0]), "r"(b[1]));
}

// ---------------- block reductions (256 threads) ---------------------------
__device__ __forceinline__ float blk_sum(float v) {
    __shared__ float sm[9];
    #pragma unroll
    for (int o = 16; o; o >>= 1) v += __shfl_xor_sync(0xffffffffu, v, o);
    if ((threadIdx.x & 31) == 0) sm[threadIdx.x >> 5] = v;
    __syncthreads();
    if (threadIdx.x == 0) {
        float t = 0.f;
        #pragma unroll
        for (int i = 0; i < 8; i++) t += sm[i];
        sm[8] = t;
    }
    __syncthreads();
    float r = sm[8];
    __syncthreads();
    return r;
}

// ---------------- small kernels --------------------------------------------
__global__ void wsum_kernel(const float* __restrict__ w, float* __restrict__ d) {
    int i = blockIdx.x * blockDim.x + threadIdx.x;
    if (i >= DQ * DD) return;
    int k = i / DD, n = i % DD;
    float s = 0.f;
    #pragma unroll
    for (int h = 0; h < 12; h++) s += w[(h * DQ + k) * DD + n];
    d[i] = to_tf32(s);
}

__global__ void pack_wqkv_kernel(const float* __restrict__ wq, const float* __restrict__ wk,
                                 const float* __restrict__ wv, float* __restrict__ d) {
    int i = blockIdx.x * blockDim.x + threadIdx.x;
    if (i >= DD * 256) return;
    int r = i >> 8, c = i & 255;
    float v = 0.f;
    if (c < 64)       v = wq[r * 64 + c];
    else if (c < 128) v = wk[r * 64 + c - 64];
    else if (c < 192) v = wv[r * 64 + c - 128];
    d[i] = to_tf32(v);
}

__global__ void round_kernel(const float* __restrict__ s, float* __restrict__ d, int n) {
    int i = blockIdx.x * blockDim.x + threadIdx.x;
    if (i < n) d[i] = to_tf32(s[i]);
}

// LayerNorm over 768 cols, fp32 -> tf32-rounded fp32. One block / row.
__global__ void ln_kernel(const float* __restrict__ x, const float* __restrict__ g,
                          const float* __restrict__ b, float* __restrict__ o) {
    long long row = blockIdx.x;
    const float* xr = x + row * DD;
    int t = threadIdx.x;
    float v0 = xr[t], v1 = xr[t + 256], v2 = xr[t + 512];
    float mu = blk_sum(v0 + v1 + v2) * (1.f / 768.f);
    float d0 = v0 - mu, d1 = v1 - mu, d2 = v2 - mu;
    float var = blk_sum(d0 * d0 + d1 * d1 + d2 * d2) * (1.f / 768.f);
    float rs = rsqrtf(var + 1e-5f);
    float* orow = o + row * DD;
    orow[t]       = to_tf32(d0 * rs * g[t]       + b[t]);
    orow[t + 256] = to_tf32(d1 * rs * g[t + 256] + b[t + 256]);
    orow[t + 512] = to_tf32(d2 * rs * g[t + 512] + b[t + 512]);
}

// ---------------- 3-stage pipelined tf32 GEMM -------------------------------
// C[M,N] = A[M,K] x B[K,N], both row-major, values already tf32-rounded.
// EPI: 2 f32 = acc+bias+res, 3 tf32(gelu(acc+bias)), 4 tf32(acc).
// BM=BN=128, BK=32, 256 threads = 8 warps (2x4) each owning a 64x32 sub-tile.
#define ASZ 4608            // 128*36 floats per stage
#define BSZ 4352            // 32*136 floats per stage
#define GEMM_SMEM ((3 * ASZ + 3 * BSZ) * 4)

template<int EPI>
__global__ __launch_bounds__(256, 2) void gemm_kernel(
    const float* __restrict__ A, const float* __restrict__ B,
    float* __restrict__ C, const float* __restrict__ bias, const float* __restrict__ res,
    int M, int N, int K, int lda, int ldb, int ldc)
{
    extern __shared__ float smx[];
    float* As = smx;                 // 3 x [128][36]
    float* Bs = smx + 3 * ASZ;       // 3 x [32][136]

    const int tid  = threadIdx.x;
    const int lane = tid & 31;
    const int warp = tid >> 5;
    const int wm = (warp >> 2) * 64, wn = (warp & 3) * 32;
    const int grp = lane >> 2, tg = lane & 3;
    const int bm = blockIdx.y * 128, bn = blockIdx.x * 128;
    const int nk = K >> 5;

    const int ar = tid >> 3, ac = (tid & 7) * 4;
    const int kr = tid >> 5, n4 = (tid & 31) * 4;

    float acc[4][4][4];
    #pragma unroll
    for (int i = 0; i < 4; i++)
        #pragma unroll
        for (int j = 0; j < 4; j++)
            #pragma unroll
            for (int l = 0; l < 4; l++) acc[i][j][l] = 0.f;

    auto stage = [&](int i) {
        const int st = i % 3;
        const int k0 = i << 5;
        float* as = As + st * ASZ;
        const float* ap = A + (long long)(bm + ar) * lda + (k0 + ac);
        #pragma unroll
        for (int p = 0; p < 4; p++)
            cp16(&as[(ar + 32 * p) * 36 + ac], ap + (long long)(32 * p) * lda);
        float* bs = Bs + st * BSZ;
        const float* bp = B + (long long)(k0 + kr) * ldb + (bn + n4);
        #pragma unroll
        for (int p = 0; p < 4; p++)
            cp16(&bs[(kr + 8 * p) * 136 + n4], bp + (long long)(8 * p) * ldb);
    };

    stage(0);
    CP_COMMIT();
    if (nk > 1) stage(1);
    CP_COMMIT();

    for (int i = 0; i < nk; i++) {
        CP_WAITG(1);               // stage i resident
        __syncthreads();
        if (i + 2 < nk) stage(i + 2);
        CP_COMMIT();

        const float* as = As + (i % 3) * ASZ;
        const float* bs = Bs + (i % 3) * BSZ;
        #pragma unroll
        for (int ks = 0; ks < 32; ks += 8) {
            uint32_t af[4][4], bfr[4][2];
            #pragma unroll
            for (int mi = 0; mi < 4; mi++) {
                int r = wm + mi * 16 + grp;
                af[mi][0] = __float_as_uint(as[r * 36 + ks + tg]);
                af[mi][1] = __float_as_uint(as[(r + 8) * 36 + ks + tg]);
                af[mi][2] = __float_as_uint(as[r * 36 + ks + tg + 4]);
                af[mi][3] = __float_as_uint(as[(r + 8) * 36 + ks + tg + 4]);
            }
            #pragma unroll
            for (int ni = 0; ni < 4; ni++) {
                int c = wn + ni * 8 + grp;
                bfr[ni][0] = __float_as_uint(bs[(ks + tg) * 136 + c]);
                bfr[ni][1] = __float_as_uint(bs[(ks + tg + 4) * 136 + c]);
            }
            #pragma unroll
            for (int mi = 0; mi < 4; mi++)
                #pragma unroll
                for (int ni = 0; ni < 4; ni++)
                    mma_tf32(acc[mi][ni], af[mi], bfr[ni]);
        }
        __syncthreads();
    }

    #pragma unroll
    for (int mi = 0; mi < 4; mi++) {
        #pragma unroll
        for (int ni = 0; ni < 4; ni++) {
            int c = bn + wn + ni * 8 + 2 * tg;
            #pragma unroll
            for (int rr2 = 0; rr2 < 2; rr2++) {
                int r = bm + wm + mi * 16 + grp + rr2 * 8;
                float v0 = acc[mi][ni][rr2 * 2], v1 = acc[mi][ni][rr2 * 2 + 1];
                long long off = (long long)r * ldc + c;
                if (EPI == 2) {
                    C[off]     = v0 + bias[c]     + res[off];
                    C[off + 1] = v1 + bias[c + 1] + res[off + 1];
                } else if (EPI == 3) {
                    float x0 = v0 + bias[c], x1 = v1 + bias[c + 1];
                    C[off]     = to_tf32(0.5f * x0 * (1.f + erff(x0 * 0.7071067811865475f)));
                    C[off + 1] = to_tf32(0.5f * x1 * (1.f + erff(x1 * 0.7071067811865475f)));
                } else {
                    C[off] = to_tf32(v0); C[off + 1] = to_tf32(v1);
                }
            }
        }
    }
}

// ---------------- flash attention ------------------------------------------
// qkv packed [8192][256] (q|k|v|pad, tf32), out g_oh [8192][64] (tf32).
// BQ=64, BKV=64, 128 threads = 4 warps x 16 q-rows. Grid (32 q-tiles, 4 batches).
#define QS  68
#define KSD 76
#define VSD 72
#define FLASH_SMEM ((64 * QS + 2 * 64 * KSD + 2 * 64 * VSD) * 4)

__global__ __launch_bounds__(128, 2) void flash_kernel(
    const float* __restrict__ qkv, float* __restrict__ oh)
{
    extern __shared__ float smx[];
    float* Qs = smx;
    float* Ks = smx + 64 * QS;
    float* Vs = Ks + 2 * 64 * KSD;

    const int tid = threadIdx.x, lane = tid & 31, warp = tid >> 5;
    const int grp = lane >> 2, tg = lane & 3;
    const int qt = blockIdx.x, batch = blockIdx.y;
    const long long rowbase = (long long)batch * SS;

    auto stage_kv = [&](int t, int st) {
        const float* base = qkv + (rowbase + t * 64) * 256;
        int rid = tid >> 1, half = tid & 1;
        const float* ks = base + rid * 256 + 64 + half * 32;
        float* kd = Ks + st * 64 * KSD + rid * KSD + half * 32;
        #pragma unroll
        for (int j = 0; j < 8; j++) cp16(kd + j * 4, ks + j * 4);
        const float* vs = base + rid * 256 + 128 + half * 32;
        float* vd = Vs + st * 64 * VSD + rid * VSD + half * 32;
        #pragma unroll
        for (int j = 0; j < 8; j++) cp16(vd + j * 4, vs + j * 4);
    };

    stage_kv(0, 0);
    CP_COMMIT();

    {
        int rid = tid >> 1, half = tid & 1;
        const float* src = qkv + (rowbase + qt * 64 + rid) * 256 + half * 32;
        #pragma unroll
        for (int j = 0; j < 8; j++) {
            float4 v = *(const float4*)(src + j * 4);
            int col = half * 32 + j * 4;
            Qs[rid * QS + col]     = v.x * 0.125f;
            Qs[rid * QS + col + 1] = v.y * 0.125f;
            Qs[rid * QS + col + 2] = v.z * 0.125f;
            Qs[rid * QS + col + 3] = v.w * 0.125f;
        }
    }
    __syncthreads();

    uint32_t qf[8][4];
    {
        int r0 = warp * 16 + grp;
        #pragma unroll
        for (int kc = 0; kc < 8; kc++) {
            qf[kc][0] = __float_as_uint(Qs[r0 * QS + kc * 8 + tg]);
            qf[kc][1] = __float_as_uint(Qs[(r0 + 8) * QS + kc * 8 + tg]);
            qf[kc][2] = __float_as_uint(Qs[r0 * QS + kc * 8 + tg + 4]);
            qf[kc][3] = __float_as_uint(Qs[(r0 + 8) * QS + kc * 8 + tg + 4]);
        }
    }

    float m0 = -1e30f, m1 = -1e30f, l0 = 0.f, l1 = 0.f;
    float oacc[8][4];
    #pragma unroll
    for (int i = 0; i < 8; i++)
        #pragma unroll
        for (int j = 0; j < 4; j++) oacc[i][j] = 0.f;

    for (int t = 0; t < 32; t++) {
        if (t + 1 < 32) stage_kv(t + 1, (t + 1) & 1);
        CP_COMMIT();
        CP_WAITG(1);
        __syncthreads();

        const float* K_ = Ks + (t & 1) * 64 * KSD;
        const float* V_ = Vs + (t & 1) * 64 * VSD;

        float sacc[8][4];
        #pragma unroll
        for (int i = 0; i < 8; i++)
            #pragma unroll
            for (int j = 0; j < 4; j++) sacc[i][j] = 0.f;

        #pragma unroll
        for (int kc = 0; kc < 8; kc++) {
            #pragma unroll
            for (int ni = 0; ni < 8; ni++) {
                uint32_t b[2];
                const float* kp = &K_[(ni * 8 + grp) * KSD + kc * 8 + tg];
                b[0] = __float_as_uint(kp[0]);
                b[1] = __float_as_uint(kp[4]);
                mma_tf32(sacc[ni], qf[kc], b);
            }
        }

        float mt0 = -1e30f, mt1 = -1e30f;
        #pragma unroll
        for (int ni = 0; ni < 8; ni++) {
            mt0 = fmaxf(mt0, fmaxf(sacc[ni][0], sacc[ni][1]));
            mt1 = fmaxf(mt1, fmaxf(sacc[ni][2], sacc[ni][3]));
        }
        mt0 = fmaxf(mt0, __shfl_xor_sync(0xffffffffu, mt0, 1));
        mt0 = fmaxf(mt0, __shfl_xor_sync(0xffffffffu, mt0, 2));
        mt1 = fmaxf(mt1, __shfl_xor_sync(0xffffffffu, mt1, 1));
        mt1 = fmaxf(mt1, __shfl_xor_sync(0xffffffffu, mt1, 2));
        float mn0 = fmaxf(m0, mt0), mn1 = fmaxf(m1, mt1);
        float a0 = __expf(m0 - mn0), a1 = __expf(m1 - mn1);
        float ps0 = 0.f, ps1 = 0.f;
        #pragma unroll
        for (int ni = 0; ni < 8; ni++) {
            sacc[ni][0] = __expf(sacc[ni][0] - mn0); ps0 += sacc[ni][0];
            sacc[ni][1] = __expf(sacc[ni][1] - mn0); ps0 += sacc[ni][1];
            sacc[ni][2] = __expf(sacc[ni][2] - mn1); ps1 += sacc[ni][2];
            sacc[ni][3] = __expf(sacc[ni][3] - mn1); ps1 += sacc[ni][3];
        }
        ps0 += __shfl_xor_sync(0xffffffffu, ps0, 1);
        ps0 += __shfl_xor_sync(0xffffffffu, ps0, 2);
        ps1 += __shfl_xor_sync(0xffffffffu, ps1, 1);
        ps1 += __shfl_xor_sync(0xffffffffu, ps1, 2);
        l0 = l0 * a0 + ps0; l1 = l1 * a1 + ps1;
        m0 = mn0; m1 = mn1;
        #pragma unroll
        for (int dn = 0; dn < 8; dn++) {
            oacc[dn][0] *= a0; oacc[dn][1] *= a0;
            oacc[dn][2] *= a1; oacc[dn][3] *= a1;
        }

        #pragma unroll
        for (int kc = 0; kc < 8; kc++) {
            const float* c = sacc[kc];
            int s0 = (lane & 28) | (tg >> 1);
            int s1 = s0 + 2;
            float x0 = __shfl_sync(0xffffffffu, c[0], s0);
            float x1 = __shfl_sync(0xffffffffu, c[1], s0);
            float y0 = __shfl_sync(0xffffffffu, c[0], s1);
            float y1 = __shfl_sync(0xffffffffu, c[1], s1);
            float z0 = __shfl_sync(0xffffffffu, c[2], s0);
            float z1 = __shfl_sync(0xffffffffu, c[3], s0);
            float w0 = __shfl_sync(0xffffffffu, c[2], s1);
            float w1 = __shfl_sync(0xffffffffu, c[3], s1);
            bool odd = (tg & 1);
            uint32_t af[4];
            af[0] = __float_as_uint(odd ? x1 : x0);
            af[1] = __float_as_uint(odd ? z1 : z0);
            af[2] = __float_as_uint(odd ? y1 : y0);
            af[3] = __float_as_uint(odd ? w1 : w0);
            #pragma unroll
            for (int dn = 0; dn < 8; dn++) {
                uint32_t b[2];
                const float* vp = &V_[(kc * 8 + tg) * VSD + dn * 8 + grp];
                b[0] = __float_as_uint(vp[0]);
                b[1] = __float_as_uint(vp[4 * VSD]);
                mma_tf32(oacc[dn], af, b);
            }
        }
        __syncthreads();
    }

    float i0 = 1.f / l0, i1 = 1.f / l1;
    int r0 = qt * 64 + warp * 16 + grp;
    float* d0 = oh + (rowbase + r0) * DQ;
    float* d1 = oh + (rowbase + r0 + 8) * DQ;
    #pragma unroll
    for (int dn = 0; dn < 8; dn++) {
        int col = dn * 8 + 2 * tg;
        *(float2*)(d0 + col) = make_float2(to_tf32(oacc[dn][0] * i0), to_tf32(oacc[dn][1] * i0));
        *(float2*)(d1 + col) = make_float2(to_tf32(oacc[dn][2] * i1), to_tf32(oacc[dn][3] * i1));
    }
}

// ---------------- launch ----------------------------------------------------
extern "C" void kernel_launch(void* const* d_in, const int* in_sizes, int n_in,
                              void* d_out, int out_size) {
    const float* x    = (const float*)d_in[0];
    const float* wq   = (const float*)d_in[1];
    const float* wk   = (const float*)d_in[2];
    const float* wv   = (const float*)d_in[3];
    const float* linw = (const float*)d_in[4];
    const float* linb = (const float*)d_in[5];
    const float* ln1g = (const float*)d_in[6];
    const float* ln1b = (const float*)d_in[7];
    const float* f1w  = (const float*)d_in[8];
    const float* f1b  = (const float*)d_in[9];
    const float* f2w  = (const float*)d_in[10];
    const float* f2b  = (const float*)d_in[11];
    float* out = (float*)d_out;

    void *p_h, *p_h2, *p_y1, *p_qkv, *p_oh, *p_a1, *p_ws, *p_wqkv, *p_f1, *p_f2;
    cudaGetSymbolAddress(&p_h,    g_h);
    cudaGetSymbolAddress(&p_h2,   g_h2);
    cudaGetSymbolAddress(&p_y1,   g_y1);
    cudaGetSymbolAddress(&p_qkv,  g_qkv);
    cudaGetSymbolAddress(&p_oh,   g_oh);
    cudaGetSymbolAddress(&p_a1,   g_a1);
    cudaGetSymbolAddress(&p_ws,   g_ws);
    cudaGetSymbolAddress(&p_wqkv, g_wqkv);
    cudaGetSymbolAddress(&p_f1,   g_f1);
    cudaGetSymbolAddress(&p_f2,   g_f2);

    cudaFuncSetAttribute(gemm_kernel<2>, cudaFuncAttributeMaxDynamicSharedMemorySize, GEMM_SMEM);
    cudaFuncSetAttribute(gemm_kernel<3>, cudaFuncAttributeMaxDynamicSharedMemorySize, GEMM_SMEM);
    cudaFuncSetAttribute(gemm_kernel<4>, cudaFuncAttributeMaxDynamicSharedMemorySize, GEMM_SMEM);
    cudaFuncSetAttribute(flash_kernel,   cudaFuncAttributeMaxDynamicSharedMemorySize, FLASH_SMEM);

    #define FP(p) ((float*)(p))
    dim3 blk(256);

    wsum_kernel<<<(DQ * DD + 255) / 256, blk>>>(linw, FP(p_ws));
    pack_wqkv_kernel<<<(DD * 256 + 255) / 256, blk>>>(wq, wk, wv, FP(p_wqkv));
    round_kernel<<<(DD * HH + 255) / 256, blk>>>(f1w, FP(p_f1), DD * HH);
    round_kernel<<<(HH * DD + 255) / 256, blk>>>(f2w, FP(p_f2), HH * DD);

    // LN1: x -> h (tf32)
    ln_kernel<<<RR, blk>>>(x, ln1g, ln1b, FP(p_h));

    // qkv = h @ wqkv_packed, tf32 store
    gemm_kernel<4><<<dim3(2, 64), blk, GEMM_SMEM>>>(FP(p_h), FP(p_wqkv), FP(p_qkv),
        nullptr, nullptr, RR, 256, DD, DD, 256, 256);

    // flash attention -> oh [8192,64] (tf32)
    flash_kernel<<<dim3(32, 4), dim3(128), FLASH_SMEM>>>(FP(p_qkv), FP(p_oh));

    // y1 = oh @ W_sum + lin_b + x  (fp32)
    gemm_kernel<2><<<dim3(6, 64), blk, GEMM_SMEM>>>(FP(p_oh), FP(p_ws), FP(p_y1),
        linb, x, RR, DD, DQ, DQ, DD, DD);

    // LN2 (reuses ln1 params, matching reference): y1 -> h2 (tf32)
    ln_kernel<<<RR, blk>>>(FP(p_y1), ln1g, ln1b, FP(p_h2));

    // a1 = gelu(h2 @ fc1_w + fc1_b)  (tf32)
    gemm_kernel<3><<<dim3(24, 64), blk, GEMM_SMEM>>>(FP(p_h2), FP(p_f1), FP(p_a1),
        f1b, nullptr, RR, HH, DD, DD, HH, HH);

    // out = a1 @ fc2_w + fc2_b + y1  (fp32)
    gemm_kernel<2><<<dim3(6, 64), blk, GEMM_SMEM>>>(FP(p_a1), FP(p_f2), out,
        f2b, FP(p_y1), RR, DD, HH, HH, DD, DD);
    #undef FP
}

// round 7
// speedup vs baseline: 1.0438x; 1.0438x over previous
#include <cuda_runtime.h>
#include <stdint.h>

// Problem dims
#define BB 4
#define SS 2048
#define DD 768
#define DQ 64
#define HH 3072
#define RR 8192   // BB*SS

// ---------------- scratch (device globals; no allocation allowed) ----------
__device__ float g_h   [RR*DD];
__device__ float g_h2  [RR*DD];
__device__ float g_y1  [RR*DD];
__device__ float g_qkv [RR*256];      // packed q|k|v|pad, row stride 256 (tf32)
__device__ float g_oh  [RR*DQ];
__device__ float g_a1  [(long long)RR*HH];
__device__ float g_ws  [DQ*DD];
__device__ float g_wqkv[DD*256];
__device__ float g_f1  [DD*HH];
__device__ float g_f2  [HH*DD];

__device__ __forceinline__ float to_tf32(float x) {
    float r;
    asm("cvt.rna.tf32.f32 %0, %1;\n" : "=f"(r) : "f"(x));
    return r;
}

__device__ __forceinline__ void cp16(void* dst, const float* src) {
    uint32_t d = (uint32_t)__cvta_generic_to_shared(dst);
    asm volatile("cp.async.cg.shared.global [%0], [%1], 16;\n" :: "r"(d), "l"(src));
}
#define CP_COMMIT() asm volatile("cp.async.commit_group;\n" ::: "memory")
#define CP_WAITG(n) asm volatile("cp.async.wait_group %0;\n" :: "n"(n) : "memory")

__device__ __forceinline__ void mma_tf32(float* c, const uint32_t* a, const uint32_t* b) {
    asm volatile(
        "mma.sync.aligned.m16n8k8.row.col.f32.tf32.tf32.f32 "
        "{%0,%1,%2,%3}, {%4,%5,%6,%7}, {%8,%9}, {%0,%1,%2,%3};\n"
        : "+f"(c[0]), "+f"(c[1]), "+f"(c[2]), "+f"(c[3])
        : "r"(a[0]), "r"(a[1]), "r"(a[2]), "r"(a[3]), "r"(b[0]), "r"(b[1]));
}

// ---------------- block reductions (256 threads) ---------------------------
__device__ __forceinline__ float blk_sum(float v) {
    __shared__ float sm[9];
    #pragma unroll
    for (int o = 16; o; o >>= 1) v += __shfl_xor_sync(0xffffffffu, v, o);
    if ((threadIdx.x & 31) == 0) sm[threadIdx.x >> 5] = v;
    __syncthreads();
    if (threadIdx.x == 0) {
        float t = 0.f;
        #pragma unroll
        for (int i = 0; i < 8; i++) t += sm[i];
        sm[8] = t;
    }
    __syncthreads();
    float r = sm[8];
    __syncthreads();
    return r;
}

// ---------------- small kernels --------------------------------------------
__global__ void wsum_kernel(const float* __restrict__ w, float* __restrict__ d) {
    int i = blockIdx.x * blockDim.x + threadIdx.x;
    if (i >= DQ * DD) return;
    int k = i / DD, n = i % DD;
    float s = 0.f;
    #pragma unroll
    for (int h = 0; h < 12; h++) s += w[(h * DQ + k) * DD + n];
    d[i] = to_tf32(s);
}

__global__ void pack_wqkv_kernel(const float* __restrict__ wq, const float* __restrict__ wk,
                                 const float* __restrict__ wv, float* __restrict__ d) {
    int i = blockIdx.x * blockDim.x + threadIdx.x;
    if (i >= DD * 256) return;
    int r = i >> 8, c = i & 255;
    float v = 0.f;
    if (c < 64)       v = wq[r * 64 + c];
    else if (c < 128) v = wk[r * 64 + c - 64];
    else if (c < 192) v = wv[r * 64 + c - 128];
    d[i] = to_tf32(v);
}

__global__ void round_kernel(const float* __restrict__ s, float* __restrict__ d, int n) {
    int i = blockIdx.x * blockDim.x + threadIdx.x;
    if (i < n) d[i] = to_tf32(s[i]);
}

// LayerNorm over 768 cols, fp32 -> tf32-rounded fp32. One block / row.
__global__ void ln_kernel(const float* __restrict__ x, const float* __restrict__ g,
                          const float* __restrict__ b, float* __restrict__ o) {
    long long row = blockIdx.x;
    const float* xr = x + row * DD;
    int t = threadIdx.x;
    float v0 = xr[t], v1 = xr[t + 256], v2 = xr[t + 512];
    float mu = blk_sum(v0 + v1 + v2) * (1.f / 768.f);
    float d0 = v0 - mu, d1 = v1 - mu, d2 = v2 - mu;
    float var = blk_sum(d0 * d0 + d1 * d1 + d2 * d2) * (1.f / 768.f);
    float rs = rsqrtf(var + 1e-5f);
    float* orow = o + row * DD;
    orow[t]       = to_tf32(d0 * rs * g[t]       + b[t]);
    orow[t + 256] = to_tf32(d1 * rs * g[t + 256] + b[t + 256]);
    orow[t + 512] = to_tf32(d2 * rs * g[t + 512] + b[t + 512]);
}

// ---------------- 2-stage pipelined tf32 GEMM, 64x64 warp tiles -------------
// C[M,N] = A[M,K] x B[K,N], row-major, values already tf32-rounded.
// EPI: 2 f32 = acc+bias+res, 3 tf32(gelu(acc+bias)), 4 tf32(acc).
// BM=BN=128, BK=32, 128 threads = 4 warps (2x2), each warp owns 64x64.
#define ASZ 4608            // 128*36 floats per stage
#define BSZ 4352            // 32*136 floats per stage
#define GEMM_SMEM ((2 * ASZ + 2 * BSZ) * 4)

template<int EPI>
__global__ __launch_bounds__(128, 2) void gemm_kernel(
    const float* __restrict__ A, const float* __restrict__ B,
    float* __restrict__ C, const float* __restrict__ bias, const float* __restrict__ res,
    int M, int N, int K, int lda, int ldb, int ldc)
{
    extern __shared__ float smx[];
    float* As = smx;                 // 2 x [128][36]
    float* Bs = smx + 2 * ASZ;       // 2 x [32][136]

    const int tid  = threadIdx.x;
    const int lane = tid & 31;
    const int warp = tid >> 5;
    const int wm = (warp >> 1) * 64, wn = (warp & 1) * 64;
    const int grp = lane >> 2, tg = lane & 3;
    const int bm = blockIdx.y * 128, bn = blockIdx.x * 128;
    const int nk = K >> 5;

    const int ar = tid >> 3, ac = (tid & 7) * 4;    // A: 16 rows/pass x 8 passes? -> rows ar+16p
    const int kr = tid >> 5, n4 = (tid & 31) * 4;   // B: rows kr+4p, cols n4

    float acc[4][8][4];
    #pragma unroll
    for (int i = 0; i < 4; i++)
        #pragma unroll
        for (int j = 0; j < 8; j++)
            #pragma unroll
            for (int l = 0; l < 4; l++) acc[i][j][l] = 0.f;

    auto stage = [&](int i, int st) {
        const int k0 = i << 5;
        float* as = As + st * ASZ;
        const float* ap = A + (long long)(bm + ar) * lda + (k0 + ac);
        #pragma unroll
        for (int p = 0; p < 8; p++)
            cp16(&as[(ar + 16 * p) * 36 + ac], ap + (long long)(16 * p) * lda);
        float* bs = Bs + st * BSZ;
        const float* bp = B + (long long)(k0 + kr) * ldb + (bn + n4);
        #pragma unroll
        for (int p = 0; p < 8; p++)
            cp16(&bs[(kr + 4 * p) * 136 + n4], bp + (long long)(4 * p) * ldb);
    };

    stage(0, 0);
    CP_COMMIT();

    for (int i = 0; i < nk; i++) {
        if (i + 1 < nk) stage(i + 1, (i + 1) & 1);
        CP_COMMIT();
        CP_WAITG(1);
        __syncthreads();

        const float* as = As + (i & 1) * ASZ;
        const float* bs = Bs + (i & 1) * BSZ;
        #pragma unroll
        for (int ks = 0; ks < 32; ks += 8) {
            uint32_t af[4][4], bfr[8][2];
            #pragma unroll
            for (int mi = 0; mi < 4; mi++) {
                int r = wm + mi * 16 + grp;
                af[mi][0] = __float_as_uint(as[r * 36 + ks + tg]);
                af[mi][1] = __float_as_uint(as[(r + 8) * 36 + ks + tg]);
                af[mi][2] = __float_as_uint(as[r * 36 + ks + tg + 4]);
                af[mi][3] = __float_as_uint(as[(r + 8) * 36 + ks + tg + 4]);
            }
            #pragma unroll
            for (int ni = 0; ni < 8; ni++) {
                int c = wn + ni * 8 + grp;
                bfr[ni][0] = __float_as_uint(bs[(ks + tg) * 136 + c]);
                bfr[ni][1] = __float_as_uint(bs[(ks + tg + 4) * 136 + c]);
            }
            #pragma unroll
            for (int mi = 0; mi < 4; mi++)
                #pragma unroll
                for (int ni = 0; ni < 8; ni++)
                    mma_tf32(acc[mi][ni], af[mi], bfr[ni]);
        }
        __syncthreads();
    }

    #pragma unroll
    for (int mi = 0; mi < 4; mi++) {
        #pragma unroll
        for (int ni = 0; ni < 8; ni++) {
            int c = bn + wn + ni * 8 + 2 * tg;
            #pragma unroll
            for (int rr2 = 0; rr2 < 2; rr2++) {
                int r = bm + wm + mi * 16 + grp + rr2 * 8;
                float v0 = acc[mi][ni][rr2 * 2], v1 = acc[mi][ni][rr2 * 2 + 1];
                long long off = (long long)r * ldc + c;
                if (EPI == 2) {
                    C[off]     = v0 + bias[c]     + res[off];
                    C[off + 1] = v1 + bias[c + 1] + res[off + 1];
                } else if (EPI == 3) {
                    float x0 = v0 + bias[c], x1 = v1 + bias[c + 1];
                    C[off]     = to_tf32(0.5f * x0 * (1.f + erff(x0 * 0.7071067811865475f)));
                    C[off + 1] = to_tf32(0.5f * x1 * (1.f + erff(x1 * 0.7071067811865475f)));
                } else {
                    C[off] = to_tf32(v0); C[off + 1] = to_tf32(v1);
                }
            }
        }
    }
}

// ---------------- flash attention ------------------------------------------
// qkv packed [8192][256] (q|k|v|pad, tf32), out g_oh [8192][64] (tf32).
// BQ=64, BKV=64, 128 threads = 4 warps x 16 q-rows. Grid (32 q-tiles, 4 batches).
#define QS  68
#define KSD 76
#define VSD 72
#define FLASH_SMEM ((64 * QS + 2 * 64 * KSD + 2 * 64 * VSD) * 4)

__global__ __launch_bounds__(128, 2) void flash_kernel(
    const float* __restrict__ qkv, float* __restrict__ oh)
{
    extern __shared__ float smx[];
    float* Qs = smx;
    float* Ks = smx + 64 * QS;
    float* Vs = Ks + 2 * 64 * KSD;

    const int tid = threadIdx.x, lane = tid & 31, warp = tid >> 5;
    const int grp = lane >> 2, tg = lane & 3;
    const int qt = blockIdx.x, batch = blockIdx.y;
    const long long rowbase = (long long)batch * SS;

    auto stage_kv = [&](int t, int st) {
        const float* base = qkv + (rowbase + t * 64) * 256;
        int rid = tid >> 1, half = tid & 1;
        const float* ks = base + rid * 256 + 64 + half * 32;
        float* kd = Ks + st * 64 * KSD + rid * KSD + half * 32;
        #pragma unroll
        for (int j = 0; j < 8; j++) cp16(kd + j * 4, ks + j * 4);
        const float* vs = base + rid * 256 + 128 + half * 32;
        float* vd = Vs + st * 64 * VSD + rid * VSD + half * 32;
        #pragma unroll
        for (int j = 0; j < 8; j++) cp16(vd + j * 4, vs + j * 4);
    };

    stage_kv(0, 0);
    CP_COMMIT();

    {
        int rid = tid >> 1, half = tid & 1;
        const float* src = qkv + (rowbase + qt * 64 + rid) * 256 + half * 32;
        #pragma unroll
        for (int j = 0; j < 8; j++) {
            float4 v = *(const float4*)(src + j * 4);
            int col = half * 32 + j * 4;
            Qs[rid * QS + col]     = v.x * 0.125f;
            Qs[rid * QS + col + 1] = v.y * 0.125f;
            Qs[rid * QS + col + 2] = v.z * 0.125f;
            Qs[rid * QS + col + 3] = v.w * 0.125f;
        }
    }
    __syncthreads();

    uint32_t qf[8][4];
    {
        int r0 = warp * 16 + grp;
        #pragma unroll
        for (int kc = 0; kc < 8; kc++) {
            qf[kc][0] = __float_as_uint(Qs[r0 * QS + kc * 8 + tg]);
            qf[kc][1] = __float_as_uint(Qs[(r0 + 8) * QS + kc * 8 + tg]);
            qf[kc][2] = __float_as_uint(Qs[r0 * QS + kc * 8 + tg + 4]);
            qf[kc][3] = __float_as_uint(Qs[(r0 + 8) * QS + kc * 8 + tg + 4]);
        }
    }

    float m0 = -1e30f, m1 = -1e30f, l0 = 0.f, l1 = 0.f;
    float oacc[8][4];
    #pragma unroll
    for (int i = 0; i < 8; i++)
        #pragma unroll
        for (int j = 0; j < 4; j++) oacc[i][j] = 0.f;

    for (int t = 0; t < 32; t++) {
        if (t + 1 < 32) stage_kv(t + 1, (t + 1) & 1);
        CP_COMMIT();
        CP_WAITG(1);
        __syncthreads();

        const float* K_ = Ks + (t & 1) * 64 * KSD;
        const float* V_ = Vs + (t & 1) * 64 * VSD;

        float sacc[8][4];
        #pragma unroll
        for (int i = 0; i < 8; i++)
            #pragma unroll
            for (int j = 0; j < 4; j++) sacc[i][j] = 0.f;

        #pragma unroll
        for (int kc = 0; kc < 8; kc++) {
            #pragma unroll
            for (int ni = 0; ni < 8; ni++) {
                uint32_t b[2];
                const float* kp = &K_[(ni * 8 + grp) * KSD + kc * 8 + tg];
                b[0] = __float_as_uint(kp[0]);
                b[1] = __float_as_uint(kp[4]);
                mma_tf32(sacc[ni], qf[kc], b);
            }
        }

        float mt0 = -1e30f, mt1 = -1e30f;
        #pragma unroll
        for (int ni = 0; ni < 8; ni++) {
            mt0 = fmaxf(mt0, fmaxf(sacc[ni][0], sacc[ni][1]));
            mt1 = fmaxf(mt1, fmaxf(sacc[ni][2], sacc[ni][3]));
        }
        mt0 = fmaxf(mt0, __shfl_xor_sync(0xffffffffu, mt0, 1));
        mt0 = fmaxf(mt0, __shfl_xor_sync(0xffffffffu, mt0, 2));
        mt1 = fmaxf(mt1, __shfl_xor_sync(0xffffffffu, mt1, 1));
        mt1 = fmaxf(mt1, __shfl_xor_sync(0xffffffffu, mt1, 2));
        float mn0 = fmaxf(m0, mt0), mn1 = fmaxf(m1, mt1);
        float a0 = __expf(m0 - mn0), a1 = __expf(m1 - mn1);
        float ps0 = 0.f, ps1 = 0.f;
        #pragma unroll
        for (int ni = 0; ni < 8; ni++) {
            sacc[ni][0] = __expf(sacc[ni][0] - mn0); ps0 += sacc[ni][0];
            sacc[ni][1] = __expf(sacc[ni][1] - mn0); ps0 += sacc[ni][1];
            sacc[ni][2] = __expf(sacc[ni][2] - mn1); ps1 += sacc[ni][2];
            sacc[ni][3] = __expf(sacc[ni][3] - mn1); ps1 += sacc[ni][3];
        }
        ps0 += __shfl_xor_sync(0xffffffffu, ps0, 1);
        ps0 += __shfl_xor_sync(0xffffffffu, ps0, 2);
        ps1 += __shfl_xor_sync(0xffffffffu, ps1, 1);
        ps1 += __shfl_xor_sync(0xffffffffu, ps1, 2);
        l0 = l0 * a0 + ps0; l1 = l1 * a1 + ps1;
        m0 = mn0; m1 = mn1;
        #pragma unroll
        for (int dn = 0; dn < 8; dn++) {
            oacc[dn][0] *= a0; oacc[dn][1] *= a0;
            oacc[dn][2] *= a1; oacc[dn][3] *= a1;
        }

        #pragma unroll
        for (int kc = 0; kc < 8; kc++) {
            const float* c = sacc[kc];
            int s0 = (lane & 28) | (tg >> 1);
            int s1 = s0 + 2;
            float x0 = __shfl_sync(0xffffffffu, c[0], s0);
            float x1 = __shfl_sync(0xffffffffu, c[1], s0);
            float y0 = __shfl_sync(0xffffffffu, c[0], s1);
            float y1 = __shfl_sync(0xffffffffu, c[1], s1);
            float z0 = __shfl_sync(0xffffffffu, c[2], s0);
            float z1 = __shfl_sync(0xffffffffu, c[3], s0);
            float w0 = __shfl_sync(0xffffffffu, c[2], s1);
            float w1 = __shfl_sync(0xffffffffu, c[3], s1);
            bool odd = (tg & 1);
            uint32_t af[4];
            af[0] = __float_as_uint(odd ? x1 : x0);
            af[1] = __float_as_uint(odd ? z1 : z0);
            af[2] = __float_as_uint(odd ? y1 : y0);
            af[3] = __float_as_uint(odd ? w1 : w0);
            #pragma unroll
            for (int dn = 0; dn < 8; dn++) {
                uint32_t b[2];
                const float* vp = &V_[(kc * 8 + tg) * VSD + dn * 8 + grp];
                b[0] = __float_as_uint(vp[0]);
                b[1] = __float_as_uint(vp[4 * VSD]);
                mma_tf32(oacc[dn], af, b);
            }
        }
        __syncthreads();
    }

    float i0 = 1.f / l0, i1 = 1.f / l1;
    int r0 = qt * 64 + warp * 16 + grp;
    float* d0 = oh + (rowbase + r0) * DQ;
    float* d1 = oh + (rowbase + r0 + 8) * DQ;
    #pragma unroll
    for (int dn = 0; dn < 8; dn++) {
        int col = dn * 8 + 2 * tg;
        *(float2*)(d0 + col) = make_float2(to_tf32(oacc[dn][0] * i0), to_tf32(oacc[dn][1] * i0));
        *(float2*)(d1 + col) = make_float2(to_tf32(oacc[dn][2] * i1), to_tf32(oacc[dn][3] * i1));
    }
}

// ---------------- launch ----------------------------------------------------
extern "C" void kernel_launch(void* const* d_in, const int* in_sizes, int n_in,
                              void* d_out, int out_size) {
    const float* x    = (const float*)d_in[0];
    const float* wq   = (const float*)d_in[1];
    const float* wk   = (const float*)d_in[2];
    const float* wv   = (const float*)d_in[3];
    const float* linw = (const float*)d_in[4];
    const float* linb = (const float*)d_in[5];
    const float* ln1g = (const float*)d_in[6];
    const float* ln1b = (const float*)d_in[7];
    const float* f1w  = (const float*)d_in[8];
    const float* f1b  = (const float*)d_in[9];
    const float* f2w  = (const float*)d_in[10];
    const float* f2b  = (const float*)d_in[11];
    float* out = (float*)d_out;

    void *p_h, *p_h2, *p_y1, *p_qkv, *p_oh, *p_a1, *p_ws, *p_wqkv, *p_f1, *p_f2;
    cudaGetSymbolAddress(&p_h,    g_h);
    cudaGetSymbolAddress(&p_h2,   g_h2);
    cudaGetSymbolAddress(&p_y1,   g_y1);
    cudaGetSymbolAddress(&p_qkv,  g_qkv);
    cudaGetSymbolAddress(&p_oh,   g_oh);
    cudaGetSymbolAddress(&p_a1,   g_a1);
    cudaGetSymbolAddress(&p_ws,   g_ws);
    cudaGetSymbolAddress(&p_wqkv, g_wqkv);
    cudaGetSymbolAddress(&p_f1,   g_f1);
    cudaGetSymbolAddress(&p_f2,   g_f2);

    cudaFuncSetAttribute(gemm_kernel<2>, cudaFuncAttributeMaxDynamicSharedMemorySize, GEMM_SMEM);
    cudaFuncSetAttribute(gemm_kernel<3>, cudaFuncAttributeMaxDynamicSharedMemorySize, GEMM_SMEM);
    cudaFuncSetAttribute(gemm_kernel<4>, cudaFuncAttributeMaxDynamicSharedMemorySize, GEMM_SMEM);
    cudaFuncSetAttribute(flash_kernel,   cudaFuncAttributeMaxDynamicSharedMemorySize, FLASH_SMEM);

    #define FP(p) ((float*)(p))
    dim3 blk(256);
    dim3 gblk(128);

    wsum_kernel<<<(DQ * DD + 255) / 256, blk>>>(linw, FP(p_ws));
    pack_wqkv_kernel<<<(DD * 256 + 255) / 256, blk>>>(wq, wk, wv, FP(p_wqkv));
    round_kernel<<<(DD * HH + 255) / 256, blk>>>(f1w, FP(p_f1), DD * HH);
    round_kernel<<<(HH * DD + 255) / 256, blk>>>(f2w, FP(p_f2), HH * DD);

    // LN1: x -> h (tf32)
    ln_kernel<<<RR, blk>>>(x, ln1g, ln1b, FP(p_h));

    // qkv = h @ wqkv_packed, tf32 store
    gemm_kernel<4><<<dim3(2, 64), gblk, GEMM_SMEM>>>(FP(p_h), FP(p_wqkv), FP(p_qkv),
        nullptr, nullptr, RR, 256, DD, DD, 256, 256);

    // flash attention -> oh [8192,64] (tf32)
    flash_kernel<<<dim3(32, 4), gblk, FLASH_SMEM>>>(FP(p_qkv), FP(p_oh));

    // y1 = oh @ W_sum + lin_b + x  (fp32)
    gemm_kernel<2><<<dim3(6, 64), gblk, GEMM_SMEM>>>(FP(p_oh), FP(p_ws), FP(p_y1),
        linb, x, RR, DD, DQ, DQ, DD, DD);

    // LN2 (reuses ln1 params, matching reference): y1 -> h2 (tf32)
    ln_kernel<<<RR, blk>>>(FP(p_y1), ln1g, ln1b, FP(p_h2));

    // a1 = gelu(h2 @ fc1_w + fc1_b)  (tf32)
    gemm_kernel<3><<<dim3(24, 64), gblk, GEMM_SMEM>>>(FP(p_h2), FP(p_f1), FP(p_a1),
        f1b, nullptr, RR, HH, DD, DD, HH, HH);

    // out = a1 @ fc2_w + fc2_b + y1  (fp32)
    gemm_kernel<2><<<dim3(6, 64), gblk, GEMM_SMEM>>>(FP(p_a1), FP(p_f2), out,
        f2b, FP(p_y1), RR, DD, HH, HH, DD, DD);
    #undef FP
}

// round 8
// speedup vs baseline: 1.2700x; 1.2166x over previous
#include <cuda_runtime.h>
#include <cuda_fp16.h>
#include <stdint.h>

// Problem dims
#define BB 4
#define SS 2048
#define DD 768
#define DQ 64
#define HH 3072
#define RR 8192   // BB*SS

// ---------------- scratch (device globals; no allocation allowed) ----------
__device__ __half g_h    [RR*DD];
__device__ __half g_h2   [RR*DD];
__device__ float  g_y1   [RR*DD];
__device__ __half g_q    [RR*DQ];          // pre-scaled by 1/8
__device__ __half g_k    [RR*DQ];
__device__ __half g_vt   [BB*DQ*SS];       // [batch][d][s]  (V transposed)
__device__ __half g_oh   [RR*DQ];
__device__ __half g_a1   [(long long)RR*HH];
__device__ __half g_wsT  [DD*DQ];          // [n=768][k=64]
__device__ __half g_wqkvT[256*DD];         // [n=256][k=768]
__device__ __half g_f1T  [HH*DD];          // [3072][768]
__device__ __half g_f2T  [DD*HH];          // [768][3072]

__device__ __forceinline__ void cp16(void* dst, const void* src) {
    uint32_t d = (uint32_t)__cvta_generic_to_shared(dst);
    asm volatile("cp.async.cg.shared.global [%0], [%1], 16;\n" :: "r"(d), "l"(src));
}
#define CP_COMMIT() asm volatile("cp.async.commit_group;\n" ::: "memory")
#define CP_WAITG(n) asm volatile("cp.async.wait_group %0;\n" :: "n"(n) : "memory")

__device__ __forceinline__ void mma_f16(float* c, const uint32_t* a, const uint32_t* b) {
    asm volatile(
        "mma.sync.aligned.m16n8k16.row.col.f32.f16.f16.f32 "
        "{%0,%1,%2,%3}, {%4,%5,%6,%7}, {%8,%9}, {%0,%1,%2,%3};\n"
        : "+f"(c[0]), "+f"(c[1]), "+f"(c[2]), "+f"(c[3])
        : "r"(a[0]), "r"(a[1]), "r"(a[2]), "r"(a[3]), "r"(b[0]), "r"(b[1]));
}

__device__ __forceinline__ uint32_t h2u(__half2 h) {
    return *reinterpret_cast<uint32_t*>(&h);
}

// ---------------- block reductions (256 threads) ---------------------------
__device__ __forceinline__ float blk_sum(float v) {
    __shared__ float sm[9];
    #pragma unroll
    for (int o = 16; o; o >>= 1) v += __shfl_xor_sync(0xffffffffu, v, o);
    if ((threadIdx.x & 31) == 0) sm[threadIdx.x >> 5] = v;
    __syncthreads();
    if (threadIdx.x == 0) {
        float t = 0.f;
        #pragma unroll
        for (int i = 0; i < 8; i++) t += sm[i];
        sm[8] = t;
    }
    __syncthreads();
    float r = sm[8];
    __syncthreads();
    return r;
}

// ---------------- prologue kernels -----------------------------------------
// WsT[n][k] = half( sum_h lin_w[h*64+k][n] )
__global__ void wsumT_kernel(const float* __restrict__ w, __half* __restrict__ d) {
    int i = blockIdx.x * blockDim.x + threadIdx.x;
    if (i >= DD * DQ) return;
    int n = i / DQ, k = i % DQ;
    float s = 0.f;
    #pragma unroll
    for (int h = 0; h < 12; h++) s += w[(h * DQ + k) * DD + n];
    d[n * DQ + k] = __float2half(s);
}

// wqkvT[c][r], c: q|k|v|pad
__global__ void pack_wqkvT_kernel(const float* __restrict__ wq, const float* __restrict__ wk,
                                  const float* __restrict__ wv, __half* __restrict__ d) {
    int i = blockIdx.x * blockDim.x + threadIdx.x;
    if (i >= 256 * DD) return;
    int c = i / DD, r = i % DD;
    float v = 0.f;
    if (c < 64)       v = wq[r * 64 + c];
    else if (c < 128) v = wk[r * 64 + c - 64];
    else if (c < 192) v = wv[r * 64 + c - 128];
    d[c * DD + r] = __float2half(v);
}

// transpose fp32 [K,N] -> half [N,K]
__global__ void transposeh_kernel(const float* __restrict__ in, __half* __restrict__ out,
                                  int K, int N) {
    __shared__ float t[32][33];
    int nb = blockIdx.x * 32, kb = blockIdx.y * 32;
    int tx = threadIdx.x, ty = threadIdx.y;
    #pragma unroll
    for (int j = 0; j < 32; j += 8)
        t[ty + j][tx] = in[(long long)(kb + ty + j) * N + nb + tx];
    __syncthreads();
    #pragma unroll
    for (int j = 0; j < 32; j += 8)
        out[(long long)(nb + ty + j) * K + kb + tx] = __float2half(t[tx][ty + j]);
}

// LayerNorm fp32 in -> half out
__global__ void ln_kernel(const float* __restrict__ x, const float* __restrict__ g,
                          const float* __restrict__ b, __half* __restrict__ o) {
    long long row = blockIdx.x;
    const float* xr = x + row * DD;
    int t = threadIdx.x;
    float v0 = xr[t], v1 = xr[t + 256], v2 = xr[t + 512];
    float mu = blk_sum(v0 + v1 + v2) * (1.f / 768.f);
    float d0 = v0 - mu, d1 = v1 - mu, d2 = v2 - mu;
    float var = blk_sum(d0 * d0 + d1 * d1 + d2 * d2) * (1.f / 768.f);
    float rs = rsqrtf(var + 1e-5f);
    __half* orow = o + row * DD;
    orow[t]       = __float2half(d0 * rs * g[t]       + b[t]);
    orow[t + 256] = __float2half(d1 * rs * g[t + 256] + b[t + 256]);
    orow[t + 512] = __float2half(d2 * rs * g[t + 512] + b[t + 512]);
}

// ---------------- fp16 GEMM core (macro-shared mainloop) --------------------
// C[M,N] = A[M,K] x BT[N,K]^T.  BM=BN=128, BK=32, 256 thr, 8 warps 64x32.
#define HSTR 40                       // smem row stride in halves
#define HSZ  (128 * HSTR)             // halves per stage
#define GEMM_SMEM (4 * HSZ * 2)       // 2 stages A + 2 stages B, bytes

// stage: thread -> row tid>>1, 32-half half-row sel tid&1
#define GEMM_STAGE(i, st) do {                                                   \
    const int k0_ = (i) << 5;                                                    \
    const __half* ap_ = A + (long long)(bm + (tid >> 1)) * lda + k0_ + (tid & 1) * 16; \
    __half* ad_ = As + (st) * HSZ + (tid >> 1) * HSTR + (tid & 1) * 16;          \
    cp16(ad_, ap_); cp16(ad_ + 8, ap_ + 8);                                      \
    const __half* bp_ = BT + (long long)(bn + (tid >> 1)) * K + k0_ + (tid & 1) * 16; \
    __half* bd_ = Bs + (st) * HSZ + (tid >> 1) * HSTR + (tid & 1) * 16;          \
    cp16(bd_, bp_); cp16(bd_ + 8, bp_ + 8);                                      \
} while (0)

#define GEMM_PRE()                                                               \
    extern __shared__ __half smh[];                                              \
    __half* As = smh;                                                            \
    __half* Bs = smh + 2 * HSZ;                                                  \
    const int tid  = threadIdx.x;                                                \
    const int lane = tid & 31;                                                   \
    const int warp = tid >> 5;                                                   \
    const int wm = (warp >> 2) * 64, wn = (warp & 3) * 32;                       \
    const int grp = lane >> 2, tg = lane & 3;                                    \
    const int bm = blockIdx.y * 128, bn = blockIdx.x * 128;                      \
    const int nk = K >> 5;                                                       \
    float acc[4][4][4];                                                          \
    _Pragma("unroll") for (int i = 0; i < 4; i++)                                \
        _Pragma("unroll") for (int j = 0; j < 4; j++)                            \
            _Pragma("unroll") for (int l = 0; l < 4; l++) acc[i][j][l] = 0.f;

#define GEMM_MAIN()                                                              \
    GEMM_STAGE(0, 0);                                                            \
    CP_COMMIT();                                                                 \
    for (int i = 0; i < nk; i++) {                                               \
        if (i + 1 < nk) GEMM_STAGE(i + 1, (i + 1) & 1);                          \
        CP_COMMIT();                                                             \
        CP_WAITG(1);                                                             \
        __syncthreads();                                                         \
        const __half* as = As + (i & 1) * HSZ;                                   \
        const __half* bs = Bs + (i & 1) * HSZ;                                   \
        _Pragma("unroll")                                                        \
        for (int ks = 0; ks < 32; ks += 16) {                                    \
            uint32_t af[4][4], bfr[4][2];                                        \
            _Pragma("unroll") for (int mi = 0; mi < 4; mi++) {                   \
                int r = wm + mi * 16 + grp;                                      \
                af[mi][0] = *(const uint32_t*)&as[r * HSTR + ks + 2 * tg];       \
                af[mi][1] = *(const uint32_t*)&as[(r + 8) * HSTR + ks + 2 * tg]; \
                af[mi][2] = *(const uint32_t*)&as[r * HSTR + ks + 8 + 2 * tg];   \
                af[mi][3] = *(const uint32_t*)&as[(r + 8) * HSTR + ks + 8 + 2 * tg]; \
            }                                                                    \
            _Pragma("unroll") for (int ni = 0; ni < 4; ni++) {                   \
                int c = wn + ni * 8 + grp;                                       \
                bfr[ni][0] = *(const uint32_t*)&bs[c * HSTR + ks + 2 * tg];      \
                bfr[ni][1] = *(const uint32_t*)&bs[c * HSTR + ks + 8 + 2 * tg];  \
            }                                                                    \
            _Pragma("unroll") for (int mi = 0; mi < 4; mi++)                     \
                _Pragma("unroll") for (int ni = 0; ni < 4; ni++)                 \
                    mma_f16(acc[mi][ni], af[mi], bfr[ni]);                       \
        }                                                                        \
        __syncthreads();                                                         \
    }

// EPI: 2 f32 = acc+bias+res, 3 half = gelu(acc+bias)
template<int EPI>
__global__ __launch_bounds__(256, 2) void gemm_kernel(
    const __half* __restrict__ A, const __half* __restrict__ BT,
    void* __restrict__ Cm, const float* __restrict__ bias, const float* __restrict__ res,
    int M, int N, int K, int lda, int ldc)
{
    GEMM_PRE();
    GEMM_MAIN();
    #pragma unroll
    for (int mi = 0; mi < 4; mi++) {
        #pragma unroll
        for (int ni = 0; ni < 4; ni++) {
            int c = bn + wn + ni * 8 + 2 * tg;
            #pragma unroll
            for (int rr2 = 0; rr2 < 2; rr2++) {
                int r = bm + wm + mi * 16 + grp + rr2 * 8;
                float v0 = acc[mi][ni][rr2 * 2], v1 = acc[mi][ni][rr2 * 2 + 1];
                long long off = (long long)r * ldc + c;
                if (EPI == 2) {
                    float* C = (float*)Cm;
                    C[off]     = v0 + bias[c]     + res[off];
                    C[off + 1] = v1 + bias[c + 1] + res[off + 1];
                } else {
                    __half* C = (__half*)Cm;
                    float x0 = v0 + bias[c], x1 = v1 + bias[c + 1];
                    C[off]     = __float2half(0.5f * x0 * (1.f + erff(x0 * 0.7071067811865475f)));
                    C[off + 1] = __float2half(0.5f * x1 * (1.f + erff(x1 * 0.7071067811865475f)));
                }
            }
        }
    }
}

// qkv GEMM: scatter epilogue -> q (scaled 1/8), k, v-transposed
__global__ __launch_bounds__(256, 2) void qkv_gemm_kernel(
    const __half* __restrict__ A, const __half* __restrict__ BT,
    __half* __restrict__ gq, __half* __restrict__ gk, __half* __restrict__ gvt,
    int M, int N, int K, int lda)
{
    GEMM_PRE();
    GEMM_MAIN();
    #pragma unroll
    for (int mi = 0; mi < 4; mi++) {
        #pragma unroll
        for (int ni = 0; ni < 4; ni++) {
            int c = bn + wn + ni * 8 + 2 * tg;
            if (c >= 192) continue;
            #pragma unroll
            for (int rr2 = 0; rr2 < 2; rr2++) {
                int r = bm + wm + mi * 16 + grp + rr2 * 8;
                float v0 = acc[mi][ni][rr2 * 2], v1 = acc[mi][ni][rr2 * 2 + 1];
                if (c < 64) {
                    *(__half2*)&gq[(long long)r * 64 + c] =
                        __floats2half2_rn(v0 * 0.125f, v1 * 0.125f);
                } else if (c < 128) {
                    *(__half2*)&gk[(long long)r * 64 + (c - 64)] = __floats2half2_rn(v0, v1);
                } else {
                    int d = c - 128, bt = r >> 11, s = r & 2047;
                    gvt[((long long)(bt * 64 + d)) * 2048 + s]     = __float2half(v0);
                    gvt[((long long)(bt * 64 + d + 1)) * 2048 + s] = __float2half(v1);
                }
            }
        }
    }
}

// ---------------- flash attention (fp16 operands, fp32 softmax) -------------
// Q/K tiles [64][64], Vt tile [d=64][kv=64]. 128 thr = 4 warps x 16 q-rows.
#define FST 72
#define FLASH_SMEM (5 * 64 * FST * 2)   // Q + 2K + 2Vt, halves*2

__global__ __launch_bounds__(128, 2) void flash_kernel(
    const __half* __restrict__ gq, const __half* __restrict__ gk,
    const __half* __restrict__ gvt, __half* __restrict__ oh)
{
    extern __shared__ __half smh[];
    __half* Qs = smh;                      // [64][72]
    __half* Ks = smh + 64 * FST;           // 2 x [64][72]
    __half* Vs = Ks + 2 * 64 * FST;        // 2 x [64][72]  (rows = d, cols = kv)

    const int tid = threadIdx.x, lane = tid & 31, warp = tid >> 5;
    const int grp = lane >> 2, tg = lane & 3;
    const int qt = blockIdx.x, batch = blockIdx.y;
    const long long rowbase = (long long)batch * SS;

    const int rid = tid >> 1, sel = tid & 1;

    auto stage_kv = [&](int t, int st) {
        const __half* kp = gk + (rowbase + t * 64 + rid) * 64 + sel * 32;
        __half* kd = Ks + st * 64 * FST + rid * FST + sel * 32;
        cp16(kd, kp); cp16(kd + 8, kp + 8); cp16(kd + 16, kp + 16); cp16(kd + 24, kp + 24);
        const __half* vp = gvt + ((long long)(batch * 64 + rid)) * 2048 + t * 64 + sel * 32;
        __half* vd = Vs + st * 64 * FST + rid * FST + sel * 32;
        cp16(vd, vp); cp16(vd + 8, vp + 8); cp16(vd + 16, vp + 16); cp16(vd + 24, vp + 24);
    };

    // stage Q + kv0 (group 0), kv1 (group 1)
    {
        const __half* qp = gq + (rowbase + qt * 64 + rid) * 64 + sel * 32;
        __half* qd = Qs + rid * FST + sel * 32;
        cp16(qd, qp); cp16(qd + 8, qp + 8); cp16(qd + 16, qp + 16); cp16(qd + 24, qp + 24);
    }
    stage_kv(0, 0);
    CP_COMMIT();
    stage_kv(1, 1);
    CP_COMMIT();
    CP_WAITG(1);          // group 0 (Q + kv0) resident
    __syncthreads();

    uint32_t qf[4][4];
    {
        int r0 = warp * 16 + grp;
        #pragma unroll
        for (int kc = 0; kc < 4; kc++) {
            qf[kc][0] = *(const uint32_t*)&Qs[r0 * FST + kc * 16 + 2 * tg];
            qf[kc][1] = *(const uint32_t*)&Qs[(r0 + 8) * FST + kc * 16 + 2 * tg];
            qf[kc][2] = *(const uint32_t*)&Qs[r0 * FST + kc * 16 + 8 + 2 * tg];
            qf[kc][3] = *(const uint32_t*)&Qs[(r0 + 8) * FST + kc * 16 + 8 + 2 * tg];
        }
    }

    float m0 = -1e30f, m1 = -1e30f, l0 = 0.f, l1 = 0.f;
    float oacc[8][4];
    #pragma unroll
    for (int i = 0; i < 8; i++)
        #pragma unroll
        for (int j = 0; j < 4; j++) oacc[i][j] = 0.f;

    for (int t = 0; t < 32; t++) {
        const __half* K_ = Ks + (t & 1) * 64 * FST;
        const __half* V_ = Vs + (t & 1) * 64 * FST;

        // S = Q @ K^T   (16 q-rows x 64 kv per warp)
        float sacc[8][4];
        #pragma unroll
        for (int i = 0; i < 8; i++)
            #pragma unroll
            for (int j = 0; j < 4; j++) sacc[i][j] = 0.f;

        #pragma unroll
        for (int kc = 0; kc < 4; kc++) {
            #pragma unroll
            for (int ni = 0; ni < 8; ni++) {
                uint32_t b[2];
                const __half* kp = &K_[(ni * 8 + grp) * FST + kc * 16 + 2 * tg];
                b[0] = *(const uint32_t*)kp;
                b[1] = *(const uint32_t*)(kp + 8);
                mma_f16(sacc[ni], qf[kc], b);
            }
        }

        // online softmax (fp32)
        float mt0 = -1e30f, mt1 = -1e30f;
        #pragma unroll
        for (int ni = 0; ni < 8; ni++) {
            mt0 = fmaxf(mt0, fmaxf(sacc[ni][0], sacc[ni][1]));
            mt1 = fmaxf(mt1, fmaxf(sacc[ni][2], sacc[ni][3]));
        }
        mt0 = fmaxf(mt0, __shfl_xor_sync(0xffffffffu, mt0, 1));
        mt0 = fmaxf(mt0, __shfl_xor_sync(0xffffffffu, mt0, 2));
        mt1 = fmaxf(mt1, __shfl_xor_sync(0xffffffffu, mt1, 1));
        mt1 = fmaxf(mt1, __shfl_xor_sync(0xffffffffu, mt1, 2));
        float mn0 = fmaxf(m0, mt0), mn1 = fmaxf(m1, mt1);
        float a0 = __expf(m0 - mn0), a1 = __expf(m1 - mn1);
        float ps0 = 0.f, ps1 = 0.f;
        #pragma unroll
        for (int ni = 0; ni < 8; ni++) {
            sacc[ni][0] = __expf(sacc[ni][0] - mn0); ps0 += sacc[ni][0];
            sacc[ni][1] = __expf(sacc[ni][1] - mn0); ps0 += sacc[ni][1];
            sacc[ni][2] = __expf(sacc[ni][2] - mn1); ps1 += sacc[ni][2];
            sacc[ni][3] = __expf(sacc[ni][3] - mn1); ps1 += sacc[ni][3];
        }
        ps0 += __shfl_xor_sync(0xffffffffu, ps0, 1);
        ps0 += __shfl_xor_sync(0xffffffffu, ps0, 2);
        ps1 += __shfl_xor_sync(0xffffffffu, ps1, 1);
        ps1 += __shfl_xor_sync(0xffffffffu, ps1, 2);
        l0 = l0 * a0 + ps0; l1 = l1 * a1 + ps1;
        m0 = mn0; m1 = mn1;
        #pragma unroll
        for (int dn = 0; dn < 8; dn++) {
            oacc[dn][0] *= a0; oacc[dn][1] *= a0;
            oacc[dn][2] *= a1; oacc[dn][3] *= a1;
        }

        // O += P @ V : P C-fragment == A-fragment (fp16 identity, no shuffles)
        #pragma unroll
        for (int kc = 0; kc < 4; kc++) {
            uint32_t af[4];
            af[0] = h2u(__floats2half2_rn(sacc[2 * kc][0],     sacc[2 * kc][1]));
            af[1] = h2u(__floats2half2_rn(sacc[2 * kc][2],     sacc[2 * kc][3]));
            af[2] = h2u(__floats2half2_rn(sacc[2 * kc + 1][0], sacc[2 * kc + 1][1]));
            af[3] = h2u(__floats2half2_rn(sacc[2 * kc + 1][2], sacc[2 * kc + 1][3]));
            #pragma unroll
            for (int dn = 0; dn < 8; dn++) {
                uint32_t b[2];
                const __half* vp = &V_[(dn * 8 + grp) * FST + kc * 16 + 2 * tg];
                b[0] = *(const uint32_t*)vp;
                b[1] = *(const uint32_t*)(vp + 8);
                mma_f16(oacc[dn], af, b);
            }
        }

        __syncthreads();                       // done reading buf t&1
        if (t + 2 < 32) stage_kv(t + 2, t & 1);
        CP_COMMIT();
        CP_WAITG(1);                           // kv(t+1) resident
        __syncthreads();
    }

    float i0 = 1.f / l0, i1 = 1.f / l1;
    int r0 = qt * 64 + warp * 16 + grp;
    __half* d0 = oh + (rowbase + r0) * DQ;
    __half* d1 = oh + (rowbase + r0 + 8) * DQ;
    #pragma unroll
    for (int dn = 0; dn < 8; dn++) {
        int col = dn * 8 + 2 * tg;
        *(__half2*)(d0 + col) = __floats2half2_rn(oacc[dn][0] * i0, oacc[dn][1] * i0);
        *(__half2*)(d1 + col) = __floats2half2_rn(oacc[dn][2] * i1, oacc[dn][3] * i1);
    }
}

// ---------------- launch ----------------------------------------------------
extern "C" void kernel_launch(void* const* d_in, const int* in_sizes, int n_in,
                              void* d_out, int out_size) {
    const float* x    = (const float*)d_in[0];
    const float* wq   = (const float*)d_in[1];
    const float* wk   = (const float*)d_in[2];
    const float* wv   = (const float*)d_in[3];
    const float* linw = (const float*)d_in[4];
    const float* linb = (const float*)d_in[5];
    const float* ln1g = (const float*)d_in[6];
    const float* ln1b = (const float*)d_in[7];
    const float* f1w  = (const float*)d_in[8];
    const float* f1b  = (const float*)d_in[9];
    const float* f2w  = (const float*)d_in[10];
    const float* f2b  = (const float*)d_in[11];
    float* out = (float*)d_out;

    void *p_h, *p_h2, *p_y1, *p_q, *p_k, *p_vt, *p_oh, *p_a1;
    void *p_wsT, *p_wqkvT, *p_f1T, *p_f2T;
    cudaGetSymbolAddress(&p_h,     g_h);
    cudaGetSymbolAddress(&p_h2,    g_h2);
    cudaGetSymbolAddress(&p_y1,    g_y1);
    cudaGetSymbolAddress(&p_q,     g_q);
    cudaGetSymbolAddress(&p_k,     g_k);
    cudaGetSymbolAddress(&p_vt,    g_vt);
    cudaGetSymbolAddress(&p_oh,    g_oh);
    cudaGetSymbolAddress(&p_a1,    g_a1);
    cudaGetSymbolAddress(&p_wsT,   g_wsT);
    cudaGetSymbolAddress(&p_wqkvT, g_wqkvT);
    cudaGetSymbolAddress(&p_f1T,   g_f1T);
    cudaGetSymbolAddress(&p_f2T,   g_f2T);

    cudaFuncSetAttribute(gemm_kernel<2>, cudaFuncAttributeMaxDynamicSharedMemorySize, GEMM_SMEM);
    cudaFuncSetAttribute(gemm_kernel<3>, cudaFuncAttributeMaxDynamicSharedMemorySize, GEMM_SMEM);
    cudaFuncSetAttribute(qkv_gemm_kernel, cudaFuncAttributeMaxDynamicSharedMemorySize, GEMM_SMEM);
    cudaFuncSetAttribute(flash_kernel,    cudaFuncAttributeMaxDynamicSharedMemorySize, FLASH_SMEM);

    #define HP(p) ((__half*)(p))
    #define FP(p) ((float*)(p))
    dim3 blk(256);

    wsumT_kernel<<<(DD * DQ + 255) / 256, blk>>>(linw, HP(p_wsT));
    pack_wqkvT_kernel<<<(256 * DD + 255) / 256, blk>>>(wq, wk, wv, HP(p_wqkvT));
    transposeh_kernel<<<dim3(HH / 32, DD / 32), dim3(32, 8)>>>(f1w, HP(p_f1T), DD, HH);
    transposeh_kernel<<<dim3(DD / 32, HH / 32), dim3(32, 8)>>>(f2w, HP(p_f2T), HH, DD);

    // LN1: x -> h (half)
    ln_kernel<<<RR, blk>>>(x, ln1g, ln1b, HP(p_h));

    // qkv: h @ wqkv -> q (1/8), k, v^T
    qkv_gemm_kernel<<<dim3(2, 64), blk, GEMM_SMEM>>>(HP(p_h), HP(p_wqkvT),
        HP(p_q), HP(p_k), HP(p_vt), RR, 256, DD, DD);

    // flash attention -> oh (half)
    flash_kernel<<<dim3(32, 4), dim3(128), FLASH_SMEM>>>(HP(p_q), HP(p_k), HP(p_vt), HP(p_oh));

    // y1 = oh @ Ws + lin_b + x  (fp32)
    gemm_kernel<2><<<dim3(6, 64), blk, GEMM_SMEM>>>(HP(p_oh), HP(p_wsT), p_y1,
        linb, x, RR, DD, DQ, DQ, DD);

    // LN2 (reuses ln1 params, matching reference): y1 -> h2 (half)
    ln_kernel<<<RR, blk>>>(FP(p_y1), ln1g, ln1b, HP(p_h2));

    // a1 = gelu(h2 @ fc1 + b1)  (half)
    gemm_kernel<3><<<dim3(24, 64), blk, GEMM_SMEM>>>(HP(p_h2), HP(p_f1T), p_a1,
        f1b, nullptr, RR, HH, DD, DD, HH);

    // out = a1 @ fc2 + b2 + y1  (fp32)
    gemm_kernel<2><<<dim3(6, 64), blk, GEMM_SMEM>>>(HP(p_a1), HP(p_f2T), out,
        f2b, FP(p_y1), RR, DD, HH, HH, DD);
    #undef HP
    #undef FP
}

// round 9
// speedup vs baseline: 1.4060x; 1.1071x over previous
#include <cuda_runtime.h>
#include <cuda_fp16.h>
#include <stdint.h>

// Problem dims
#define BB 4
#define SS 2048
#define DD 768
#define DQ 64
#define HH 3072
#define RR 8192   // BB*SS

// ---------------- scratch (device globals; no allocation allowed) ----------
__device__ __half g_h    [RR*DD];
__device__ __half g_h2   [RR*DD];
__device__ float  g_y1   [RR*DD];
__device__ __half g_q    [RR*DQ];          // pre-scaled by 1/8
__device__ __half g_k    [RR*DQ];
__device__ __half g_vt   [BB*DQ*SS];       // [batch][d][s]  (V transposed)
__device__ __half g_oh   [RR*DQ];
__device__ __half g_a1   [(long long)RR*HH];
__device__ __half g_wsT  [DD*DQ];          // [n=768][k=64]
__device__ __half g_wqkvT[256*DD];         // [n=256][k=768]
__device__ __half g_f1T  [HH*DD];          // [3072][768]
__device__ __half g_f2T  [DD*HH];          // [768][3072]

__device__ __forceinline__ void cp16(void* dst, const void* src) {
    uint32_t d = (uint32_t)__cvta_generic_to_shared(dst);
    asm volatile("cp.async.cg.shared.global [%0], [%1], 16;\n" :: "r"(d), "l"(src));
}
#define CP_COMMIT() asm volatile("cp.async.commit_group;\n" ::: "memory")
#define CP_WAITG(n) asm volatile("cp.async.wait_group %0;\n" :: "n"(n) : "memory")

__device__ __forceinline__ void mma_f16(float* c, const uint32_t* a, const uint32_t* b) {
    asm volatile(
        "mma.sync.aligned.m16n8k16.row.col.f32.f16.f16.f32 "
        "{%0,%1,%2,%3}, {%4,%5,%6,%7}, {%8,%9}, {%0,%1,%2,%3};\n"
        : "+f"(c[0]), "+f"(c[1]), "+f"(c[2]), "+f"(c[3])
        : "r"(a[0]), "r"(a[1]), "r"(a[2]), "r"(a[3]), "r"(b[0]), "r"(b[1]));
}

__device__ __forceinline__ void ldsm4(uint32_t& r0, uint32_t& r1, uint32_t& r2, uint32_t& r3,
                                      uint32_t a) {
    asm volatile("ldmatrix.sync.aligned.m8n8.x4.shared.b16 {%0,%1,%2,%3}, [%4];"
        : "=r"(r0), "=r"(r1), "=r"(r2), "=r"(r3) : "r"(a));
}

__device__ __forceinline__ uint32_t h2u(__half2 h) {
    return *reinterpret_cast<uint32_t*>(&h);
}

// ---------------- block reductions (256 threads) ---------------------------
__device__ __forceinline__ float blk_sum(float v) {
    __shared__ float sm[9];
    #pragma unroll
    for (int o = 16; o; o >>= 1) v += __shfl_xor_sync(0xffffffffu, v, o);
    if ((threadIdx.x & 31) == 0) sm[threadIdx.x >> 5] = v;
    __syncthreads();
    if (threadIdx.x == 0) {
        float t = 0.f;
        #pragma unroll
        for (int i = 0; i < 8; i++) t += sm[i];
        sm[8] = t;
    }
    __syncthreads();
    float r = sm[8];
    __syncthreads();
    return r;
}

// ---------------- prologue kernels -----------------------------------------
__global__ void wsumT_kernel(const float* __restrict__ w, __half* __restrict__ d) {
    int i = blockIdx.x * blockDim.x + threadIdx.x;
    if (i >= DD * DQ) return;
    int n = i / DQ, k = i % DQ;
    float s = 0.f;
    #pragma unroll
    for (int h = 0; h < 12; h++) s += w[(h * DQ + k) * DD + n];
    d[n * DQ + k] = __float2half(s);
}

__global__ void pack_wqkvT_kernel(const float* __restrict__ wq, const float* __restrict__ wk,
                                  const float* __restrict__ wv, __half* __restrict__ d) {
    int i = blockIdx.x * blockDim.x + threadIdx.x;
    if (i >= 256 * DD) return;
    int c = i / DD, r = i % DD;
    float v = 0.f;
    if (c < 64)       v = wq[r * 64 + c];
    else if (c < 128) v = wk[r * 64 + c - 64];
    else if (c < 192) v = wv[r * 64 + c - 128];
    d[c * DD + r] = __float2half(v);
}

__global__ void transposeh_kernel(const float* __restrict__ in, __half* __restrict__ out,
                                  int K, int N) {
    __shared__ float t[32][33];
    int nb = blockIdx.x * 32, kb = blockIdx.y * 32;
    int tx = threadIdx.x, ty = threadIdx.y;
    #pragma unroll
    for (int j = 0; j < 32; j += 8)
        t[ty + j][tx] = in[(long long)(kb + ty + j) * N + nb + tx];
    __syncthreads();
    #pragma unroll
    for (int j = 0; j < 32; j += 8)
        out[(long long)(nb + ty + j) * K + kb + tx] = __float2half(t[tx][ty + j]);
}

__global__ void ln_kernel(const float* __restrict__ x, const float* __restrict__ g,
                          const float* __restrict__ b, __half* __restrict__ o) {
    long long row = blockIdx.x;
    const float* xr = x + row * DD;
    int t = threadIdx.x;
    float v0 = xr[t], v1 = xr[t + 256], v2 = xr[t + 512];
    float mu = blk_sum(v0 + v1 + v2) * (1.f / 768.f);
    float d0 = v0 - mu, d1 = v1 - mu, d2 = v2 - mu;
    float var = blk_sum(d0 * d0 + d1 * d1 + d2 * d2) * (1.f / 768.f);
    float rs = rsqrtf(var + 1e-5f);
    __half* orow = o + row * DD;
    orow[t]       = __float2half(d0 * rs * g[t]       + b[t]);
    orow[t + 256] = __float2half(d1 * rs * g[t + 256] + b[t + 256]);
    orow[t + 512] = __float2half(d2 * rs * g[t + 512] + b[t + 512]);
}

// ---------------- fp16 GEMM core (macro-shared mainloop, LDSM loads) --------
// C[M,N] = A[M,K] x BT[N,K]^T.  BM=BN=128, BK=32, 256 thr, 8 warps 64x32.
#define HSTR 40
#define HSZ  (128 * HSTR)
#define GEMM_SMEM (4 * HSZ * 2)

#define GEMM_STAGE(i, st) do {                                                   \
    const int k0_ = (i) << 5;                                                    \
    const __half* ap_ = A + (long long)(bm + (tid >> 1)) * lda + k0_ + (tid & 1) * 16; \
    __half* ad_ = As + (st) * HSZ + (tid >> 1) * HSTR + (tid & 1) * 16;          \
    cp16(ad_, ap_); cp16(ad_ + 8, ap_ + 8);                                      \
    const __half* bp_ = BT + (long long)(bn + (tid >> 1)) * K + k0_ + (tid & 1) * 16; \
    __half* bd_ = Bs + (st) * HSZ + (tid >> 1) * HSTR + (tid & 1) * 16;          \
    cp16(bd_, bp_); cp16(bd_ + 8, bp_ + 8);                                      \
} while (0)

#define GEMM_PRE()                                                               \
    extern __shared__ __half smh[];                                              \
    __half* As = smh;                                                            \
    __half* Bs = smh + 2 * HSZ;                                                  \
    const int tid  = threadIdx.x;                                                \
    const int lane = tid & 31;                                                   \
    const int warp = tid >> 5;                                                   \
    const int wm = (warp >> 2) * 64, wn = (warp & 3) * 32;                       \
    const int grp = lane >> 2, tg = lane & 3;                                    \
    const int bm = blockIdx.y * 128, bn = blockIdx.x * 128;                      \
    const int nk = K >> 5;                                                       \
    const uint32_t As_u = (uint32_t)__cvta_generic_to_shared(As);                \
    const uint32_t Bs_u = (uint32_t)__cvta_generic_to_shared(Bs);                \
    /* LDSM lane offsets (bytes): A: +8 rows if lane[3], +8 cols if lane[4] */   \
    const uint32_t a_loff = (uint32_t)(((wm + (lane & 7) + ((lane >> 3) & 1) * 8) * HSTR \
                               + ((lane >> 4) & 1) * 8) * 2);                    \
    const uint32_t b_loff = (uint32_t)(((wn + (lane & 7) + ((lane >> 4) & 1) * 8) * HSTR \
                               + ((lane >> 3) & 1) * 8) * 2);                    \
    float acc[4][4][4];                                                          \
    _Pragma("unroll") for (int i = 0; i < 4; i++)                                \
        _Pragma("unroll") for (int j = 0; j < 4; j++)                            \
            _Pragma("unroll") for (int l = 0; l < 4; l++) acc[i][j][l] = 0.f;

#define GEMM_MAIN()                                                              \
    GEMM_STAGE(0, 0);                                                            \
    CP_COMMIT();                                                                 \
    for (int i = 0; i < nk; i++) {                                               \
        if (i + 1 < nk) GEMM_STAGE(i + 1, (i + 1) & 1);                          \
        CP_COMMIT();                                                             \
        CP_WAITG(1);                                                             \
        __syncthreads();                                                         \
        const uint32_t ab = As_u + (uint32_t)((i & 1) * HSZ * 2) + a_loff;       \
        const uint32_t bb = Bs_u + (uint32_t)((i & 1) * HSZ * 2) + b_loff;       \
        _Pragma("unroll")                                                        \
        for (int ks = 0; ks < 32; ks += 16) {                                    \
            uint32_t af[4][4], bfr[4][2];                                        \
            _Pragma("unroll") for (int mi = 0; mi < 4; mi++)                     \
                ldsm4(af[mi][0], af[mi][1], af[mi][2], af[mi][3],                \
                      ab + (uint32_t)((mi * 16 * HSTR + ks) * 2));               \
            ldsm4(bfr[0][0], bfr[0][1], bfr[1][0], bfr[1][1],                    \
                  bb + (uint32_t)(ks * 2));                                      \
            ldsm4(bfr[2][0], bfr[2][1], bfr[3][0], bfr[3][1],                    \
                  bb + (uint32_t)((16 * HSTR + ks) * 2));                        \
            _Pragma("unroll") for (int mi = 0; mi < 4; mi++)                     \
                _Pragma("unroll") for (int ni = 0; ni < 4; ni++)                 \
                    mma_f16(acc[mi][ni], af[mi], bfr[ni]);                       \
        }                                                                        \
        __syncthreads();                                                         \
    }

// EPI: 2 f32 = acc+bias+res, 3 half = gelu(acc+bias)
template<int EPI>
__global__ __launch_bounds__(256, 2) void gemm_kernel(
    const __half* __restrict__ A, const __half* __restrict__ BT,
    void* __restrict__ Cm, const float* __restrict__ bias, const float* __restrict__ res,
    int M, int N, int K, int lda, int ldc)
{
    GEMM_PRE();
    GEMM_MAIN();
    #pragma unroll
    for (int mi = 0; mi < 4; mi++) {
        #pragma unroll
        for (int ni = 0; ni < 4; ni++) {
            int c = bn + wn + ni * 8 + 2 * tg;
            #pragma unroll
            for (int rr2 = 0; rr2 < 2; rr2++) {
                int r = bm + wm + mi * 16 + grp + rr2 * 8;
                float v0 = acc[mi][ni][rr2 * 2], v1 = acc[mi][ni][rr2 * 2 + 1];
                long long off = (long long)r * ldc + c;
                if (EPI == 2) {
                    float* C = (float*)Cm;
                    C[off]     = v0 + bias[c]     + res[off];
                    C[off + 1] = v1 + bias[c + 1] + res[off + 1];
                } else {
                    __half* C = (__half*)Cm;
                    float x0 = v0 + bias[c], x1 = v1 + bias[c + 1];
                    C[off]     = __float2half(0.5f * x0 * (1.f + erff(x0 * 0.7071067811865475f)));
                    C[off + 1] = __float2half(0.5f * x1 * (1.f + erff(x1 * 0.7071067811865475f)));
                }
            }
        }
    }
}

// qkv GEMM: scatter epilogue -> q (scaled 1/8), k, v-transposed
__global__ __launch_bounds__(256, 2) void qkv_gemm_kernel(
    const __half* __restrict__ A, const __half* __restrict__ BT,
    __half* __restrict__ gq, __half* __restrict__ gk, __half* __restrict__ gvt,
    int M, int N, int K, int lda)
{
    GEMM_PRE();
    GEMM_MAIN();
    #pragma unroll
    for (int mi = 0; mi < 4; mi++) {
        #pragma unroll
        for (int ni = 0; ni < 4; ni++) {
            int c = bn + wn + ni * 8 + 2 * tg;
            if (c >= 192) continue;
            #pragma unroll
            for (int rr2 = 0; rr2 < 2; rr2++) {
                int r = bm + wm + mi * 16 + grp + rr2 * 8;
                float v0 = acc[mi][ni][rr2 * 2], v1 = acc[mi][ni][rr2 * 2 + 1];
                if (c < 64) {
                    *(__half2*)&gq[(long long)r * 64 + c] =
                        __floats2half2_rn(v0 * 0.125f, v1 * 0.125f);
                } else if (c < 128) {
                    *(__half2*)&gk[(long long)r * 64 + (c - 64)] = __floats2half2_rn(v0, v1);
                } else {
                    int d = c - 128, bt = r >> 11, s = r & 2047;
                    gvt[((long long)(bt * 64 + d)) * 2048 + s]     = __float2half(v0);
                    gvt[((long long)(bt * 64 + d + 1)) * 2048 + s] = __float2half(v1);
                }
            }
        }
    }
}

// ---------------- flash attention (fp16, LDSM K/V loads) --------------------
#define FST 72
#define FLASH_SMEM (5 * 64 * FST * 2)

__global__ __launch_bounds__(128, 2) void flash_kernel(
    const __half* __restrict__ gq, const __half* __restrict__ gk,
    const __half* __restrict__ gvt, __half* __restrict__ oh)
{
    extern __shared__ __half smh[];
    __half* Qs = smh;                      // [64][72]
    __half* Ks = smh + 64 * FST;           // 2 x [64][72]
    __half* Vs = Ks + 2 * 64 * FST;        // 2 x [64][72]  (rows = d, cols = kv)

    const int tid = threadIdx.x, lane = tid & 31, warp = tid >> 5;
    const int grp = lane >> 2, tg = lane & 3;
    const int qt = blockIdx.x, batch = blockIdx.y;
    const long long rowbase = (long long)batch * SS;

    const int rid = tid >> 1, sel = tid & 1;

    const uint32_t Ks_u = (uint32_t)__cvta_generic_to_shared(Ks);
    const uint32_t Vs_u = (uint32_t)__cvta_generic_to_shared(Vs);
    // LDSM lane offset for B-style frags over stride-FST rows (wn = 0)
    const uint32_t kv_loff = (uint32_t)((((lane & 7) + ((lane >> 4) & 1) * 8) * FST
                               + ((lane >> 3) & 1) * 8) * 2);

    auto stage_kv = [&](int t, int st) {
        const __half* kp = gk + (rowbase + t * 64 + rid) * 64 + sel * 32;
        __half* kd = Ks + st * 64 * FST + rid * FST + sel * 32;
        cp16(kd, kp); cp16(kd + 8, kp + 8); cp16(kd + 16, kp + 16); cp16(kd + 24, kp + 24);
        const __half* vp = gvt + ((long long)(batch * 64 + rid)) * 2048 + t * 64 + sel * 32;
        __half* vd = Vs + st * 64 * FST + rid * FST + sel * 32;
        cp16(vd, vp); cp16(vd + 8, vp + 8); cp16(vd + 16, vp + 16); cp16(vd + 24, vp + 24);
    };

    {
        const __half* qp = gq + (rowbase + qt * 64 + rid) * 64 + sel * 32;
        __half* qd = Qs + rid * FST + sel * 32;
        cp16(qd, qp); cp16(qd + 8, qp + 8); cp16(qd + 16, qp + 16); cp16(qd + 24, qp + 24);
    }
    stage_kv(0, 0);
    CP_COMMIT();
    stage_kv(1, 1);
    CP_COMMIT();
    CP_WAITG(1);
    __syncthreads();

    // Q fragments via LDSM (A-style over stride-FST rows)
    uint32_t qf[4][4];
    {
        const uint32_t Qs_u = (uint32_t)__cvta_generic_to_shared(Qs);
        const uint32_t q_loff = (uint32_t)(((warp * 16 + (lane & 7) + ((lane >> 3) & 1) * 8) * FST
                                 + ((lane >> 4) & 1) * 8) * 2);
        #pragma unroll
        for (int kc = 0; kc < 4; kc++)
            ldsm4(qf[kc][0], qf[kc][1], qf[kc][2], qf[kc][3],
                  Qs_u + q_loff + (uint32_t)(kc * 16 * 2));
    }

    float m0 = -1e30f, m1 = -1e30f, l0 = 0.f, l1 = 0.f;
    float oacc[8][4];
    #pragma unroll
    for (int i = 0; i < 8; i++)
        #pragma unroll
        for (int j = 0; j < 4; j++) oacc[i][j] = 0.f;

    for (int t = 0; t < 32; t++) {
        const uint32_t Kb = Ks_u + (uint32_t)((t & 1) * 64 * FST * 2) + kv_loff;
        const uint32_t Vb = Vs_u + (uint32_t)((t & 1) * 64 * FST * 2) + kv_loff;

        // S = Q @ K^T
        float sacc[8][4];
        #pragma unroll
        for (int i = 0; i < 8; i++)
            #pragma unroll
            for (int j = 0; j < 4; j++) sacc[i][j] = 0.f;

        #pragma unroll
        for (int kc = 0; kc < 4; kc++) {
            uint32_t kb[8][2];
            #pragma unroll
            for (int nb = 0; nb < 4; nb++)
                ldsm4(kb[2 * nb][0], kb[2 * nb][1], kb[2 * nb + 1][0], kb[2 * nb + 1][1],
                      Kb + (uint32_t)((nb * 16 * FST + kc * 16) * 2));
            #pragma unroll
            for (int ni = 0; ni < 8; ni++)
                mma_f16(sacc[ni], qf[kc], kb[ni]);
        }

        // online softmax (fp32)
        float mt0 = -1e30f, mt1 = -1e30f;
        #pragma unroll
        for (int ni = 0; ni < 8; ni++) {
            mt0 = fmaxf(mt0, fmaxf(sacc[ni][0], sacc[ni][1]));
            mt1 = fmaxf(mt1, fmaxf(sacc[ni][2], sacc[ni][3]));
        }
        mt0 = fmaxf(mt0, __shfl_xor_sync(0xffffffffu, mt0, 1));
        mt0 = fmaxf(mt0, __shfl_xor_sync(0xffffffffu, mt0, 2));
        mt1 = fmaxf(mt1, __shfl_xor_sync(0xffffffffu, mt1, 1));
        mt1 = fmaxf(mt1, __shfl_xor_sync(0xffffffffu, mt1, 2));
        float mn0 = fmaxf(m0, mt0), mn1 = fmaxf(m1, mt1);
        float a0 = __expf(m0 - mn0), a1 = __expf(m1 - mn1);
        float ps0 = 0.f, ps1 = 0.f;
        #pragma unroll
        for (int ni = 0; ni < 8; ni++) {
            sacc[ni][0] = __expf(sacc[ni][0] - mn0); ps0 += sacc[ni][0];
            sacc[ni][1] = __expf(sacc[ni][1] - mn0); ps0 += sacc[ni][1];
            sacc[ni][2] = __expf(sacc[ni][2] - mn1); ps1 += sacc[ni][2];
            sacc[ni][3] = __expf(sacc[ni][3] - mn1); ps1 += sacc[ni][3];
        }
        ps0 += __shfl_xor_sync(0xffffffffu, ps0, 1);
        ps0 += __shfl_xor_sync(0xffffffffu, ps0, 2);
        ps1 += __shfl_xor_sync(0xffffffffu, ps1, 1);
        ps1 += __shfl_xor_sync(0xffffffffu, ps1, 2);
        l0 = l0 * a0 + ps0; l1 = l1 * a1 + ps1;
        m0 = mn0; m1 = mn1;
        #pragma unroll
        for (int dn = 0; dn < 8; dn++) {
            oacc[dn][0] *= a0; oacc[dn][1] *= a0;
            oacc[dn][2] *= a1; oacc[dn][3] *= a1;
        }

        // O += P @ V : P C-frag == A-frag in fp16 (no shuffles)
        #pragma unroll
        for (int kc = 0; kc < 4; kc++) {
            uint32_t af[4];
            af[0] = h2u(__floats2half2_rn(sacc[2 * kc][0],     sacc[2 * kc][1]));
            af[1] = h2u(__floats2half2_rn(sacc[2 * kc][2],     sacc[2 * kc][3]));
            af[2] = h2u(__floats2half2_rn(sacc[2 * kc + 1][0], sacc[2 * kc + 1][1]));
            af[3] = h2u(__floats2half2_rn(sacc[2 * kc + 1][2], sacc[2 * kc + 1][3]));
            uint32_t vb[8][2];
            #pragma unroll
            for (int nb = 0; nb < 4; nb++)
                ldsm4(vb[2 * nb][0], vb[2 * nb][1], vb[2 * nb + 1][0], vb[2 * nb + 1][1],
                      Vb + (uint32_t)((nb * 16 * FST + kc * 16) * 2));
            #pragma unroll
            for (int dn = 0; dn < 8; dn++)
                mma_f16(oacc[dn], af, vb[dn]);
        }

        __syncthreads();
        if (t + 2 < 32) stage_kv(t + 2, t & 1);
        CP_COMMIT();
        CP_WAITG(1);
        __syncthreads();
    }

    float i0 = 1.f / l0, i1 = 1.f / l1;
    int r0 = qt * 64 + warp * 16 + grp;
    __half* d0 = oh + (rowbase + r0) * DQ;
    __half* d1 = oh + (rowbase + r0 + 8) * DQ;
    #pragma unroll
    for (int dn = 0; dn < 8; dn++) {
        int col = dn * 8 + 2 * tg;
        *(__half2*)(d0 + col) = __floats2half2_rn(oacc[dn][0] * i0, oacc[dn][1] * i0);
        *(__half2*)(d1 + col) = __floats2half2_rn(oacc[dn][2] * i1, oacc[dn][3] * i1);
    }
}

// ---------------- launch ----------------------------------------------------
extern "C" void kernel_launch(void* const* d_in, const int* in_sizes, int n_in,
                              void* d_out, int out_size) {
    const float* x    = (const float*)d_in[0];
    const float* wq   = (const float*)d_in[1];
    const float* wk   = (const float*)d_in[2];
    const float* wv   = (const float*)d_in[3];
    const float* linw = (const float*)d_in[4];
    const float* linb = (const float*)d_in[5];
    const float* ln1g = (const float*)d_in[6];
    const float* ln1b = (const float*)d_in[7];
    const float* f1w  = (const float*)d_in[8];
    const float* f1b  = (const float*)d_in[9];
    const float* f2w  = (const float*)d_in[10];
    const float* f2b  = (const float*)d_in[11];
    float* out = (float*)d_out;

    void *p_h, *p_h2, *p_y1, *p_q, *p_k, *p_vt, *p_oh, *p_a1;
    void *p_wsT, *p_wqkvT, *p_f1T, *p_f2T;
    cudaGetSymbolAddress(&p_h,     g_h);
    cudaGetSymbolAddress(&p_h2,    g_h2);
    cudaGetSymbolAddress(&p_y1,    g_y1);
    cudaGetSymbolAddress(&p_q,     g_q);
    cudaGetSymbolAddress(&p_k,     g_k);
    cudaGetSymbolAddress(&p_vt,    g_vt);
    cudaGetSymbolAddress(&p_oh,    g_oh);
    cudaGetSymbolAddress(&p_a1,    g_a1);
    cudaGetSymbolAddress(&p_wsT,   g_wsT);
    cudaGetSymbolAddress(&p_wqkvT, g_wqkvT);
    cudaGetSymbolAddress(&p_f1T,   g_f1T);
    cudaGetSymbolAddress(&p_f2T,   g_f2T);

    cudaFuncSetAttribute(gemm_kernel<2>, cudaFuncAttributeMaxDynamicSharedMemorySize, GEMM_SMEM);
    cudaFuncSetAttribute(gemm_kernel<3>, cudaFuncAttributeMaxDynamicSharedMemorySize, GEMM_SMEM);
    cudaFuncSetAttribute(qkv_gemm_kernel, cudaFuncAttributeMaxDynamicSharedMemorySize, GEMM_SMEM);
    cudaFuncSetAttribute(flash_kernel,    cudaFuncAttributeMaxDynamicSharedMemorySize, FLASH_SMEM);

    #define HP(p) ((__half*)(p))
    #define FP(p) ((float*)(p))
    dim3 blk(256);

    wsumT_kernel<<<(DD * DQ + 255) / 256, blk>>>(linw, HP(p_wsT));
    pack_wqkvT_kernel<<<(256 * DD + 255) / 256, blk>>>(wq, wk, wv, HP(p_wqkvT));
    transposeh_kernel<<<dim3(HH / 32, DD / 32), dim3(32, 8)>>>(f1w, HP(p_f1T), DD, HH);
    transposeh_kernel<<<dim3(DD / 32, HH / 32), dim3(32, 8)>>>(f2w, HP(p_f2T), HH, DD);

    // LN1: x -> h (half)
    ln_kernel<<<RR, blk>>>(x, ln1g, ln1b, HP(p_h));

    // qkv: h @ wqkv -> q (1/8), k, v^T
    qkv_gemm_kernel<<<dim3(2, 64), blk, GEMM_SMEM>>>(HP(p_h), HP(p_wqkvT),
        HP(p_q), HP(p_k), HP(p_vt), RR, 256, DD, DD);

    // flash attention -> oh (half)
    flash_kernel<<<dim3(32, 4), dim3(128), FLASH_SMEM>>>(HP(p_q), HP(p_k), HP(p_vt), HP(p_oh));

    // y1 = oh @ Ws + lin_b + x  (fp32)
    gemm_kernel<2><<<dim3(6, 64), blk, GEMM_SMEM>>>(HP(p_oh), HP(p_wsT), p_y1,
        linb, x, RR, DD, DQ, DQ, DD);

    // LN2 (reuses ln1 params, matching reference): y1 -> h2 (half)
    ln_kernel<<<RR, blk>>>(FP(p_y1), ln1g, ln1b, HP(p_h2));

    // a1 = gelu(h2 @ fc1 + b1)  (half)
    gemm_kernel<3><<<dim3(24, 64), blk, GEMM_SMEM>>>(HP(p_h2), HP(p_f1T), p_a1,
        f1b, nullptr, RR, HH, DD, DD, HH);

    // out = a1 @ fc2 + b2 + y1  (fp32)
    gemm_kernel<2><<<dim3(6, 64), blk, GEMM_SMEM>>>(HP(p_a1), HP(p_f2T), out,
        f2b, FP(p_y1), RR, DD, HH, HH, DD);
    #undef HP
    #undef FP
}

// round 10
// speedup vs baseline: 1.4641x; 1.0414x over previous
#include <cuda_runtime.h>
#include <cuda_fp16.h>
#include <stdint.h>

// Problem dims
#define BB 4
#define SS 2048
#define DD 768
#define DQ 64
#define HH 3072
#define RR 8192   // BB*SS

// ---------------- scratch (device globals; no allocation allowed) ----------
__device__ __half g_h    [RR*DD];
__device__ __half g_h2   [RR*DD];
__device__ float  g_y1   [RR*DD];
__device__ __half g_q    [RR*DQ];          // pre-scaled by 1/8
__device__ __half g_k    [RR*DQ];
__device__ __half g_vt   [BB*DQ*SS];       // [batch][d][s]  (V transposed)
__device__ __half g_oh   [RR*DQ];
__device__ __half g_a1   [(long long)RR*HH];
__device__ __half g_wsT  [DD*DQ];          // [n=768][k=64]
__device__ __half g_wqkvT[256*DD];         // [n=256][k=768]
__device__ __half g_f1T  [HH*DD];          // [3072][768]
__device__ __half g_f2T  [DD*HH];          // [768][3072]

__device__ __forceinline__ void cp16(void* dst, const void* src) {
    uint32_t d = (uint32_t)__cvta_generic_to_shared(dst);
    asm volatile("cp.async.cg.shared.global [%0], [%1], 16;\n" :: "r"(d), "l"(src));
}
#define CP_COMMIT() asm volatile("cp.async.commit_group;\n" ::: "memory")
#define CP_WAITG(n) asm volatile("cp.async.wait_group %0;\n" :: "n"(n) : "memory")

__device__ __forceinline__ void mma_f16(float* c, const uint32_t* a, const uint32_t* b) {
    asm volatile(
        "mma.sync.aligned.m16n8k16.row.col.f32.f16.f16.f32 "
        "{%0,%1,%2,%3}, {%4,%5,%6,%7}, {%8,%9}, {%0,%1,%2,%3};\n"
        : "+f"(c[0]), "+f"(c[1]), "+f"(c[2]), "+f"(c[3])
        : "r"(a[0]), "r"(a[1]), "r"(a[2]), "r"(a[3]), "r"(b[0]), "r"(b[1]));
}

__device__ __forceinline__ void ldsm4(uint32_t& r0, uint32_t& r1, uint32_t& r2, uint32_t& r3,
                                      uint32_t a) {
    asm volatile("ldmatrix.sync.aligned.m8n8.x4.shared.b16 {%0,%1,%2,%3}, [%4];"
        : "=r"(r0), "=r"(r1), "=r"(r2), "=r"(r3) : "r"(a));
}

__device__ __forceinline__ uint32_t h2u(__half2 h) {
    return *reinterpret_cast<uint32_t*>(&h);
}

// ---------------- block reductions (256 threads) ---------------------------
__device__ __forceinline__ float blk_sum(float v) {
    __shared__ float sm[9];
    #pragma unroll
    for (int o = 16; o; o >>= 1) v += __shfl_xor_sync(0xffffffffu, v, o);
    if ((threadIdx.x & 31) == 0) sm[threadIdx.x >> 5] = v;
    __syncthreads();
    if (threadIdx.x == 0) {
        float t = 0.f;
        #pragma unroll
        for (int i = 0; i < 8; i++) t += sm[i];
        sm[8] = t;
    }
    __syncthreads();
    float r = sm[8];
    __syncthreads();
    return r;
}

// ---------------- prologue kernels -----------------------------------------
__global__ void wsumT_kernel(const float* __restrict__ w, __half* __restrict__ d) {
    int i = blockIdx.x * blockDim.x + threadIdx.x;
    if (i >= DD * DQ) return;
    int n = i / DQ, k = i % DQ;
    float s = 0.f;
    #pragma unroll
    for (int h = 0; h < 12; h++) s += w[(h * DQ + k) * DD + n];
    d[n * DQ + k] = __float2half(s);
}

__global__ void pack_wqkvT_kernel(const float* __restrict__ wq, const float* __restrict__ wk,
                                  const float* __restrict__ wv, __half* __restrict__ d) {
    int i = blockIdx.x * blockDim.x + threadIdx.x;
    if (i >= 256 * DD) return;
    int c = i / DD, r = i % DD;
    float v = 0.f;
    if (c < 64)       v = wq[r * 64 + c];
    else if (c < 128) v = wk[r * 64 + c - 64];
    else if (c < 192) v = wv[r * 64 + c - 128];
    d[c * DD + r] = __float2half(v);
}

__global__ void transposeh_kernel(const float* __restrict__ in, __half* __restrict__ out,
                                  int K, int N) {
    __shared__ float t[32][33];
    int nb = blockIdx.x * 32, kb = blockIdx.y * 32;
    int tx = threadIdx.x, ty = threadIdx.y;
    #pragma unroll
    for (int j = 0; j < 32; j += 8)
        t[ty + j][tx] = in[(long long)(kb + ty + j) * N + nb + tx];
    __syncthreads();
    #pragma unroll
    for (int j = 0; j < 32; j += 8)
        out[(long long)(nb + ty + j) * K + kb + tx] = __float2half(t[tx][ty + j]);
}

__global__ void ln_kernel(const float* __restrict__ x, const float* __restrict__ g,
                          const float* __restrict__ b, __half* __restrict__ o) {
    long long row = blockIdx.x;
    const float* xr = x + row * DD;
    int t = threadIdx.x;
    float v0 = xr[t], v1 = xr[t + 256], v2 = xr[t + 512];
    float mu = blk_sum(v0 + v1 + v2) * (1.f / 768.f);
    float d0 = v0 - mu, d1 = v1 - mu, d2 = v2 - mu;
    float var = blk_sum(d0 * d0 + d1 * d1 + d2 * d2) * (1.f / 768.f);
    float rs = rsqrtf(var + 1e-5f);
    __half* orow = o + row * DD;
    orow[t]       = __float2half(d0 * rs * g[t]       + b[t]);
    orow[t + 256] = __float2half(d1 * rs * g[t + 256] + b[t + 256]);
    orow[t + 512] = __float2half(d2 * rs * g[t + 512] + b[t + 512]);
}

// ---------------- fp16 GEMM core (3-stage pipeline, 1 barrier/tile) ---------
// C[M,N] = A[M,K] x BT[N,K]^T.  BM=BN=128, BK=32, 256 thr, 8 warps 64x32.
#define HSTR 40
#define HSZ  (128 * HSTR)
#define GEMM_SMEM (6 * HSZ * 2)     // 3 stages x (A + B), bytes

#define GEMM_STAGE(i, st) do {                                                   \
    const int k0_ = (i) << 5;                                                    \
    const __half* ap_ = A + (long long)(bm + (tid >> 1)) * lda + k0_ + (tid & 1) * 16; \
    __half* ad_ = As + (st) * HSZ + (tid >> 1) * HSTR + (tid & 1) * 16;          \
    cp16(ad_, ap_); cp16(ad_ + 8, ap_ + 8);                                      \
    const __half* bp_ = BT + (long long)(bn + (tid >> 1)) * K + k0_ + (tid & 1) * 16; \
    __half* bd_ = Bs + (st) * HSZ + (tid >> 1) * HSTR + (tid & 1) * 16;          \
    cp16(bd_, bp_); cp16(bd_ + 8, bp_ + 8);                                      \
} while (0)

#define GEMM_PRE()                                                               \
    extern __shared__ __half smh[];                                              \
    __half* As = smh;                                                            \
    __half* Bs = smh + 3 * HSZ;                                                  \
    const int tid  = threadIdx.x;                                                \
    const int lane = tid & 31;                                                   \
    const int warp = tid >> 5;                                                   \
    const int wm = (warp >> 2) * 64, wn = (warp & 3) * 32;                       \
    const int grp = lane >> 2, tg = lane & 3;                                    \
    const int bm = blockIdx.y * 128, bn = blockIdx.x * 128;                      \
    const int nk = K >> 5;                                                       \
    const uint32_t As_u = (uint32_t)__cvta_generic_to_shared(As);                \
    const uint32_t Bs_u = (uint32_t)__cvta_generic_to_shared(Bs);                \
    const uint32_t a_loff = (uint32_t)(((wm + (lane & 7) + ((lane >> 3) & 1) * 8) * HSTR \
                               + ((lane >> 4) & 1) * 8) * 2);                    \
    const uint32_t b_loff = (uint32_t)(((wn + (lane & 7) + ((lane >> 4) & 1) * 8) * HSTR \
                               + ((lane >> 3) & 1) * 8) * 2);                    \
    float acc[4][4][4];                                                          \
    _Pragma("unroll") for (int i = 0; i < 4; i++)                                \
        _Pragma("unroll") for (int j = 0; j < 4; j++)                            \
            _Pragma("unroll") for (int l = 0; l < 4; l++) acc[i][j][l] = 0.f;

#define GEMM_MAIN()                                                              \
    GEMM_STAGE(0, 0);                                                            \
    CP_COMMIT();                                                                 \
    GEMM_STAGE(1, 1);                                                            \
    CP_COMMIT();                                                                 \
    for (int i = 0; i < nk; i++) {                                               \
        CP_WAITG(1);              /* stage i resident */                         \
        __syncthreads();          /* + all warps done with buf (i-1)%3 */        \
        if (i + 2 < nk) GEMM_STAGE(i + 2, (i + 2) % 3);                          \
        CP_COMMIT();              /* empty group at tail keeps ordering */       \
        const uint32_t ab = As_u + (uint32_t)((i % 3) * HSZ * 2) + a_loff;       \
        const uint32_t bb = Bs_u + (uint32_t)((i % 3) * HSZ * 2) + b_loff;       \
        _Pragma("unroll")                                                        \
        for (int ks = 0; ks < 32; ks += 16) {                                    \
            uint32_t af[4][4], bfr[4][2];                                        \
            _Pragma("unroll") for (int mi = 0; mi < 4; mi++)                     \
                ldsm4(af[mi][0], af[mi][1], af[mi][2], af[mi][3],                \
                      ab + (uint32_t)((mi * 16 * HSTR + ks) * 2));               \
            ldsm4(bfr[0][0], bfr[0][1], bfr[1][0], bfr[1][1],                    \
                  bb + (uint32_t)(ks * 2));                                      \
            ldsm4(bfr[2][0], bfr[2][1], bfr[3][0], bfr[3][1],                    \
                  bb + (uint32_t)((16 * HSTR + ks) * 2));                        \
            _Pragma("unroll") for (int mi = 0; mi < 4; mi++)                     \
                _Pragma("unroll") for (int ni = 0; ni < 4; ni++)                 \
                    mma_f16(acc[mi][ni], af[mi], bfr[ni]);                       \
        }                                                                        \
    }

// EPI: 2 f32 = acc+bias+res, 3 half = gelu(acc+bias)
template<int EPI>
__global__ __launch_bounds__(256, 2) void gemm_kernel(
    const __half* __restrict__ A, const __half* __restrict__ BT,
    void* __restrict__ Cm, const float* __restrict__ bias, const float* __restrict__ res,
    int M, int N, int K, int lda, int ldc)
{
    GEMM_PRE();
    GEMM_MAIN();
    #pragma unroll
    for (int mi = 0; mi < 4; mi++) {
        #pragma unroll
        for (int ni = 0; ni < 4; ni++) {
            int c = bn + wn + ni * 8 + 2 * tg;
            #pragma unroll
            for (int rr2 = 0; rr2 < 2; rr2++) {
                int r = bm + wm + mi * 16 + grp + rr2 * 8;
                float v0 = acc[mi][ni][rr2 * 2], v1 = acc[mi][ni][rr2 * 2 + 1];
                long long off = (long long)r * ldc + c;
                if (EPI == 2) {
                    float* C = (float*)Cm;
                    C[off]     = v0 + bias[c]     + res[off];
                    C[off + 1] = v1 + bias[c + 1] + res[off + 1];
                } else {
                    __half* C = (__half*)Cm;
                    float x0 = v0 + bias[c], x1 = v1 + bias[c + 1];
                    C[off]     = __float2half(0.5f * x0 * (1.f + erff(x0 * 0.7071067811865475f)));
                    C[off + 1] = __float2half(0.5f * x1 * (1.f + erff(x1 * 0.7071067811865475f)));
                }
            }
        }
    }
}

// qkv GEMM: scatter epilogue -> q (scaled 1/8), k, v-transposed
__global__ __launch_bounds__(256, 2) void qkv_gemm_kernel(
    const __half* __restrict__ A, const __half* __restrict__ BT,
    __half* __restrict__ gq, __half* __restrict__ gk, __half* __restrict__ gvt,
    int M, int N, int K, int lda)
{
    GEMM_PRE();
    GEMM_MAIN();
    #pragma unroll
    for (int mi = 0; mi < 4; mi++) {
        #pragma unroll
        for (int ni = 0; ni < 4; ni++) {
            int c = bn + wn + ni * 8 + 2 * tg;
            if (c >= 192) continue;
            #pragma unroll
            for (int rr2 = 0; rr2 < 2; rr2++) {
                int r = bm + wm + mi * 16 + grp + rr2 * 8;
                float v0 = acc[mi][ni][rr2 * 2], v1 = acc[mi][ni][rr2 * 2 + 1];
                if (c < 64) {
                    *(__half2*)&gq[(long long)r * 64 + c] =
                        __floats2half2_rn(v0 * 0.125f, v1 * 0.125f);
                } else if (c < 128) {
                    *(__half2*)&gk[(long long)r * 64 + (c - 64)] = __floats2half2_rn(v0, v1);
                } else {
                    int d = c - 128, bt = r >> 11, s = r & 2047;
                    gvt[((long long)(bt * 64 + d)) * 2048 + s]     = __float2half(v0);
                    gvt[((long long)(bt * 64 + d + 1)) * 2048 + s] = __float2half(v1);
                }
            }
        }
    }
}

// ---------------- flash attention (fp16, LDSM K/V loads) --------------------
#define FST 72
#define FLASH_SMEM (5 * 64 * FST * 2)

__global__ __launch_bounds__(128, 2) void flash_kernel(
    const __half* __restrict__ gq, const __half* __restrict__ gk,
    const __half* __restrict__ gvt, __half* __restrict__ oh)
{
    extern __shared__ __half smh[];
    __half* Qs = smh;                      // [64][72]
    __half* Ks = smh + 64 * FST;           // 2 x [64][72]
    __half* Vs = Ks + 2 * 64 * FST;        // 2 x [64][72]  (rows = d, cols = kv)

    const int tid = threadIdx.x, lane = tid & 31, warp = tid >> 5;
    const int grp = lane >> 2, tg = lane & 3;
    const int qt = blockIdx.x, batch = blockIdx.y;
    const long long rowbase = (long long)batch * SS;

    const int rid = tid >> 1, sel = tid & 1;

    const uint32_t Ks_u = (uint32_t)__cvta_generic_to_shared(Ks);
    const uint32_t Vs_u = (uint32_t)__cvta_generic_to_shared(Vs);
    const uint32_t kv_loff = (uint32_t)((((lane & 7) + ((lane >> 4) & 1) * 8) * FST
                               + ((lane >> 3) & 1) * 8) * 2);

    auto stage_kv = [&](int t, int st) {
        const __half* kp = gk + (rowbase + t * 64 + rid) * 64 + sel * 32;
        __half* kd = Ks + st * 64 * FST + rid * FST + sel * 32;
        cp16(kd, kp); cp16(kd + 8, kp + 8); cp16(kd + 16, kp + 16); cp16(kd + 24, kp + 24);
        const __half* vp = gvt + ((long long)(batch * 64 + rid)) * 2048 + t * 64 + sel * 32;
        __half* vd = Vs + st * 64 * FST + rid * FST + sel * 32;
        cp16(vd, vp); cp16(vd + 8, vp + 8); cp16(vd + 16, vp + 16); cp16(vd + 24, vp + 24);
    };

    {
        const __half* qp = gq + (rowbase + qt * 64 + rid) * 64 + sel * 32;
        __half* qd = Qs + rid * FST + sel * 32;
        cp16(qd, qp); cp16(qd + 8, qp + 8); cp16(qd + 16, qp + 16); cp16(qd + 24, qp + 24);
    }
    stage_kv(0, 0);
    CP_COMMIT();
    stage_kv(1, 1);
    CP_COMMIT();
    CP_WAITG(1);
    __syncthreads();

    uint32_t qf[4][4];
    {
        const uint32_t Qs_u = (uint32_t)__cvta_generic_to_shared(Qs);
        const uint32_t q_loff = (uint32_t)(((warp * 16 + (lane & 7) + ((lane >> 3) & 1) * 8) * FST
                                 + ((lane >> 4) & 1) * 8) * 2);
        #pragma unroll
        for (int kc = 0; kc < 4; kc++)
            ldsm4(qf[kc][0], qf[kc][1], qf[kc][2], qf[kc][3],
                  Qs_u + q_loff + (uint32_t)(kc * 16 * 2));
    }

    float m0 = -1e30f, m1 = -1e30f, l0 = 0.f, l1 = 0.f;
    float oacc[8][4];
    #pragma unroll
    for (int i = 0; i < 8; i++)
        #pragma unroll
        for (int j = 0; j < 4; j++) oacc[i][j] = 0.f;

    for (int t = 0; t < 32; t++) {
        const uint32_t Kb = Ks_u + (uint32_t)((t & 1) * 64 * FST * 2) + kv_loff;
        const uint32_t Vb = Vs_u + (uint32_t)((t & 1) * 64 * FST * 2) + kv_loff;

        float sacc[8][4];
        #pragma unroll
        for (int i = 0; i < 8; i++)
            #pragma unroll
            for (int j = 0; j < 4; j++) sacc[i][j] = 0.f;

        #pragma unroll
        for (int kc = 0; kc < 4; kc++) {
            uint32_t kb[8][2];
            #pragma unroll
            for (int nb = 0; nb < 4; nb++)
                ldsm4(kb[2 * nb][0], kb[2 * nb][1], kb[2 * nb + 1][0], kb[2 * nb + 1][1],
                      Kb + (uint32_t)((nb * 16 * FST + kc * 16) * 2));
            #pragma unroll
            for (int ni = 0; ni < 8; ni++)
                mma_f16(sacc[ni], qf[kc], kb[ni]);
        }

        float mt0 = -1e30f, mt1 = -1e30f;
        #pragma unroll
        for (int ni = 0; ni < 8; ni++) {
            mt0 = fmaxf(mt0, fmaxf(sacc[ni][0], sacc[ni][1]));
            mt1 = fmaxf(mt1, fmaxf(sacc[ni][2], sacc[ni][3]));
        }
        mt0 = fmaxf(mt0, __shfl_xor_sync(0xffffffffu, mt0, 1));
        mt0 = fmaxf(mt0, __shfl_xor_sync(0xffffffffu, mt0, 2));
        mt1 = fmaxf(mt1, __shfl_xor_sync(0xffffffffu, mt1, 1));
        mt1 = fmaxf(mt1, __shfl_xor_sync(0xffffffffu, mt1, 2));
        float mn0 = fmaxf(m0, mt0), mn1 = fmaxf(m1, mt1);
        float a0 = __expf(m0 - mn0), a1 = __expf(m1 - mn1);
        float ps0 = 0.f, ps1 = 0.f;
        #pragma unroll
        for (int ni = 0; ni < 8; ni++) {
            sacc[ni][0] = __expf(sacc[ni][0] - mn0); ps0 += sacc[ni][0];
            sacc[ni][1] = __expf(sacc[ni][1] - mn0); ps0 += sacc[ni][1];
            sacc[ni][2] = __expf(sacc[ni][2] - mn1); ps1 += sacc[ni][2];
            sacc[ni][3] = __expf(sacc[ni][3] - mn1); ps1 += sacc[ni][3];
        }
        ps0 += __shfl_xor_sync(0xffffffffu, ps0, 1);
        ps0 += __shfl_xor_sync(0xffffffffu, ps0, 2);
        ps1 += __shfl_xor_sync(0xffffffffu, ps1, 1);
        ps1 += __shfl_xor_sync(0xffffffffu, ps1, 2);
        l0 = l0 * a0 + ps0; l1 = l1 * a1 + ps1;
        m0 = mn0; m1 = mn1;
        #pragma unroll
        for (int dn = 0; dn < 8; dn++) {
            oacc[dn][0] *= a0; oacc[dn][1] *= a0;
            oacc[dn][2] *= a1; oacc[dn][3] *= a1;
        }

        #pragma unroll
        for (int kc = 0; kc < 4; kc++) {
            uint32_t af[4];
            af[0] = h2u(__floats2half2_rn(sacc[2 * kc][0],     sacc[2 * kc][1]));
            af[1] = h2u(__floats2half2_rn(sacc[2 * kc][2],     sacc[2 * kc][3]));
            af[2] = h2u(__floats2half2_rn(sacc[2 * kc + 1][0], sacc[2 * kc + 1][1]));
            af[3] = h2u(__floats2half2_rn(sacc[2 * kc + 1][2], sacc[2 * kc + 1][3]));
            uint32_t vb[8][2];
            #pragma unroll
            for (int nb = 0; nb < 4; nb++)
                ldsm4(vb[2 * nb][0], vb[2 * nb][1], vb[2 * nb + 1][0], vb[2 * nb + 1][1],
                      Vb + (uint32_t)((nb * 16 * FST + kc * 16) * 2));
            #pragma unroll
            for (int dn = 0; dn < 8; dn++)
                mma_f16(oacc[dn], af, vb[dn]);
        }

        __syncthreads();
        if (t + 2 < 32) stage_kv(t + 2, t & 1);
        CP_COMMIT();
        CP_WAITG(1);
        __syncthreads();
    }

    float i0 = 1.f / l0, i1 = 1.f / l1;
    int r0 = qt * 64 + warp * 16 + grp;
    __half* d0 = oh + (rowbase + r0) * DQ;
    __half* d1 = oh + (rowbase + r0 + 8) * DQ;
    #pragma unroll
    for (int dn = 0; dn < 8; dn++) {
        int col = dn * 8 + 2 * tg;
        *(__half2*)(d0 + col) = __floats2half2_rn(oacc[dn][0] * i0, oacc[dn][1] * i0);
        *(__half2*)(d1 + col) = __floats2half2_rn(oacc[dn][2] * i1, oacc[dn][3] * i1);
    }
}

// ---------------- launch ----------------------------------------------------
extern "C" void kernel_launch(void* const* d_in, const int* in_sizes, int n_in,
                              void* d_out, int out_size) {
    const float* x    = (const float*)d_in[0];
    const float* wq   = (const float*)d_in[1];
    const float* wk   = (const float*)d_in[2];
    const float* wv   = (const float*)d_in[3];
    const float* linw = (const float*)d_in[4];
    const float* linb = (const float*)d_in[5];
    const float* ln1g = (const float*)d_in[6];
    const float* ln1b = (const float*)d_in[7];
    const float* f1w  = (const float*)d_in[8];
    const float* f1b  = (const float*)d_in[9];
    const float* f2w  = (const float*)d_in[10];
    const float* f2b  = (const float*)d_in[11];
    float* out = (float*)d_out;

    void *p_h, *p_h2, *p_y1, *p_q, *p_k, *p_vt, *p_oh, *p_a1;
    void *p_wsT, *p_wqkvT, *p_f1T, *p_f2T;
    cudaGetSymbolAddress(&p_h,     g_h);
    cudaGetSymbolAddress(&p_h2,    g_h2);
    cudaGetSymbolAddress(&p_y1,    g_y1);
    cudaGetSymbolAddress(&p_q,     g_q);
    cudaGetSymbolAddress(&p_k,     g_k);
    cudaGetSymbolAddress(&p_vt,    g_vt);
    cudaGetSymbolAddress(&p_oh,    g_oh);
    cudaGetSymbolAddress(&p_a1,    g_a1);
    cudaGetSymbolAddress(&p_wsT,   g_wsT);
    cudaGetSymbolAddress(&p_wqkvT, g_wqkvT);
    cudaGetSymbolAddress(&p_f1T,   g_f1T);
    cudaGetSymbolAddress(&p_f2T,   g_f2T);

    cudaFuncSetAttribute(gemm_kernel<2>, cudaFuncAttributeMaxDynamicSharedMemorySize, GEMM_SMEM);
    cudaFuncSetAttribute(gemm_kernel<3>, cudaFuncAttributeMaxDynamicSharedMemorySize, GEMM_SMEM);
    cudaFuncSetAttribute(qkv_gemm_kernel, cudaFuncAttributeMaxDynamicSharedMemorySize, GEMM_SMEM);
    cudaFuncSetAttribute(flash_kernel,    cudaFuncAttributeMaxDynamicSharedMemorySize, FLASH_SMEM);

    #define HP(p) ((__half*)(p))
    #define FP(p) ((float*)(p))
    dim3 blk(256);

    wsumT_kernel<<<(DD * DQ + 255) / 256, blk>>>(linw, HP(p_wsT));
    pack_wqkvT_kernel<<<(256 * DD + 255) / 256, blk>>>(wq, wk, wv, HP(p_wqkvT));
    transposeh_kernel<<<dim3(HH / 32, DD / 32), dim3(32, 8)>>>(f1w, HP(p_f1T), DD, HH);
    transposeh_kernel<<<dim3(DD / 32, HH / 32), dim3(32, 8)>>>(f2w, HP(p_f2T), HH, DD);

    // LN1: x -> h (half)
    ln_kernel<<<RR, blk>>>(x, ln1g, ln1b, HP(p_h));

    // qkv: h @ wqkv -> q (1/8), k, v^T
    qkv_gemm_kernel<<<dim3(2, 64), blk, GEMM_SMEM>>>(HP(p_h), HP(p_wqkvT),
        HP(p_q), HP(p_k), HP(p_vt), RR, 256, DD, DD);

    // flash attention -> oh (half)
    flash_kernel<<<dim3(32, 4), dim3(128), FLASH_SMEM>>>(HP(p_q), HP(p_k), HP(p_vt), HP(p_oh));

    // y1 = oh @ Ws + lin_b + x  (fp32)
    gemm_kernel<2><<<dim3(6, 64), blk, GEMM_SMEM>>>(HP(p_oh), HP(p_wsT), p_y1,
        linb, x, RR, DD, DQ, DQ, DD);

    // LN2 (reuses ln1 params, matching reference): y1 -> h2 (half)
    ln_kernel<<<RR, blk>>>(FP(p_y1), ln1g, ln1b, HP(p_h2));

    // a1 = gelu(h2 @ fc1 + b1)  (half)
    gemm_kernel<3><<<dim3(24, 64), blk, GEMM_SMEM>>>(HP(p_h2), HP(p_f1T), p_a1,
        f1b, nullptr, RR, HH, DD, DD, HH);

    // out = a1 @ fc2 + b2 + y1  (fp32)
    gemm_kernel<2><<<dim3(6, 64), blk, GEMM_SMEM>>>(HP(p_a1), HP(p_f2T), out,
        f2b, FP(p_y1), RR, DD, HH, HH, DD);
    #undef HP
    #undef FP
}